// round 8
// baseline (speedup 1.0000x reference)
#include <cuda_runtime.h>
#include <cuda_bf16.h>
#include <cstdint>

#define NN  50000
#define NE  800000
#define NET 850000   // NE + NN self loops

typedef __nv_bfloat16 bf16;

// ---------------- scratch (static device globals; no allocs allowed) ----------
__device__ float g_h1[(size_t)NN * 256];   // x @ W1 (f32, gather source)
__device__ float g_h2[(size_t)NN * 512];   // f1 @ W2 (f32, gather source)
__device__ bf16  g_xhi[(size_t)NN * 128], g_xlo[(size_t)NN * 128];
__device__ bf16  g_f1hi[(size_t)NN * 256], g_f1lo[(size_t)NN * 256];
__device__ bf16  g_w1hi[256 * 128], g_w1lo[256 * 128];     // W1^T [N=256,K=128]
__device__ bf16  g_w2hi[512 * 256], g_w2lo[512 * 256];     // W2^T [N=512,K=256]
__device__ float g_es1[NN * 2], g_ed1[NN * 2];
__device__ float g_es2[NN * 2], g_ed2[NN * 2];
__device__ float g_ew[(size_t)2 * NET];    // per-edge (head0,head1) leaky logits
__device__ int   g_deg[NN];
__device__ int   g_off[NN + 1];
__device__ int   g_cur[NN];
__device__ int   g_csr[NET];               // src per CSR slot (grouped by dst)

// ---------------- PTX helpers (arch-generic: ldmatrix + mma.sync) -------------
__device__ __forceinline__ uint32_t s2u(const void* p) {
    uint32_t a;
    asm("{ .reg .u64 t; cvta.to.shared.u64 t, %1; cvt.u32.u64 %0, t; }"
        : "=r"(a) : "l"(p));
    return a;
}

__device__ __forceinline__ void ldsm4(uint32_t* r, uint32_t addr) {
    asm volatile("ldmatrix.sync.aligned.m8n8.x4.shared.b16 {%0,%1,%2,%3}, [%4];"
                 : "=r"(r[0]), "=r"(r[1]), "=r"(r[2]), "=r"(r[3]) : "r"(addr));
}

__device__ __forceinline__ void mma16816(float* d, const uint32_t* a,
                                         uint32_t b0, uint32_t b1) {
    asm volatile(
        "mma.sync.aligned.m16n8k16.row.col.f32.bf16.bf16.f32 "
        "{%0,%1,%2,%3}, {%4,%5,%6,%7}, {%8,%9}, {%0,%1,%2,%3};"
        : "+f"(d[0]), "+f"(d[1]), "+f"(d[2]), "+f"(d[3])
        : "r"(a[0]), "r"(a[1]), "r"(a[2]), "r"(a[3]), "r"(b0), "r"(b1));
}

// ---------------- fp32 -> bf16 hi/lo split (+fused g_deg zero) ----------------
__global__ void k_split(const float* __restrict__ in, bf16* __restrict__ hi,
                        bf16* __restrict__ lo, int n) {
    int i = blockIdx.x * blockDim.x + threadIdx.x;
    if (i < NN) g_deg[i] = 0;
    if (i >= n) return;
    float v = in[i];
    bf16 h = __float2bfloat16(v);
    hi[i] = h;
    lo[i] = __float2bfloat16(v - __bfloat162float(h));
}

// W[K,N] row-major -> Wt[N,K] hi/lo split
__global__ void k_splitT(const float* __restrict__ W, bf16* __restrict__ hiT,
                         bf16* __restrict__ loT, int K, int N) {
    int i = blockIdx.x * blockDim.x + threadIdx.x;
    if (i >= K * N) return;
    int k = i / N, n = i % N;
    float v = W[i];
    bf16 h = __float2bfloat16(v);
    hiT[(size_t)n * K + k] = h;
    loT[(size_t)n * K + k] = __float2bfloat16(v - __bfloat162float(h));
}

// ---------------- CSR build (proven versions) ---------------------------------
__global__ void k_hist(const int* __restrict__ dst) {
    int i = blockIdx.x * blockDim.x + threadIdx.x;
    if (i >= NET) return;
    int d = (i < NE) ? dst[i] : (i - NE);
    atomicAdd(&g_deg[d], 1);
}

__global__ void k_scan() {
    __shared__ int sums[1024];
    const int t  = threadIdx.x;
    const int CH = (NN + 1023) / 1024;
    int b = t * CH, e = b + CH; if (e > NN) e = NN; if (b > NN) b = NN;
    int s = 0;
    for (int i = b; i < e; i++) s += g_deg[i];
    sums[t] = s;
    __syncthreads();
    for (int off = 1; off < 1024; off <<= 1) {
        int v = (t >= off) ? sums[t - off] : 0;
        __syncthreads();
        sums[t] += v;
        __syncthreads();
    }
    int pre = (t == 0) ? 0 : sums[t - 1];
    for (int i = b; i < e; i++) {
        g_off[i] = pre;
        g_cur[i] = pre;
        pre += g_deg[i];
    }
    if (t == 1023) g_off[NN] = NET;
}

__global__ void k_fill(const int* __restrict__ src, const int* __restrict__ dst) {
    int i = blockIdx.x * blockDim.x + threadIdx.x;
    if (i >= NET) return;
    int s, d;
    if (i < NE) { s = src[i]; d = dst[i]; }
    else        { s = d = i - NE; }
    int pos = atomicAdd(&g_cur[d], 1);
    g_csr[pos] = s;
}

// ---------------- HMMA GEMM (proven): C = A @ Wt^T ----------------------------
// bf16 split: C = Ahi*Bhi + Ahi*Blo + Alo*Bhi (fp32 acc), fp32 output.
// 128x128 tile / CTA, 8 warps (2x4), warp tile 64x32, BK=32, reg prefetch.
#define RS 40   // smem row stride in bf16 elements (80B, ldmatrix conflict-free)

__global__ __launch_bounds__(256)
void k_mma(const bf16* __restrict__ Ahi, const bf16* __restrict__ Alo,
           const bf16* __restrict__ Bhi, const bf16* __restrict__ Blo,
           float* __restrict__ C, int M, int Nn, int K) {
    __shared__ __align__(16) bf16 sAh[128 * RS];
    __shared__ __align__(16) bf16 sAl[128 * RS];
    __shared__ __align__(16) bf16 sBh[128 * RS];
    __shared__ __align__(16) bf16 sBl[128 * RS];

    const int tid = threadIdx.x, lane = tid & 31, wid = tid >> 5;
    const int bm = blockIdx.y * 128, bn = blockIdx.x * 128;
    const int wm = (wid & 1) * 64;
    const int wn = (wid >> 1) * 32;

    int lrow[2], lc4[2];
    size_t aoffs[2], boffs[2];
#pragma unroll
    for (int j = 0; j < 2; j++) {
        int idx = tid + j * 256;
        lrow[j] = idx >> 2;
        lc4[j]  = idx & 3;
        int ra = bm + lrow[j]; if (ra >= M) ra = M - 1;
        aoffs[j] = (size_t)ra * K + lc4[j] * 8;
        boffs[j] = (size_t)(bn + lrow[j]) * K + lc4[j] * 8;
    }

    const int li = lane >> 3, l8 = lane & 7;
    const uint32_t aA = (uint32_t)(((wm + (li & 1) * 8 + l8) * RS + (li >> 1) * 8) * 2);
    const uint32_t aB = (uint32_t)(((wn + (li >> 1) * 8 + l8) * RS + (li & 1) * 8) * 2);
    const uint32_t bAh = s2u(sAh) + aA, bAl = s2u(sAl) + aA;
    const uint32_t bBh = s2u(sBh) + aB, bBl = s2u(sBl) + aB;

    float acc[4][4][4];
#pragma unroll
    for (int i = 0; i < 4; i++)
#pragma unroll
        for (int j = 0; j < 4; j++)
#pragma unroll
            for (int k = 0; k < 4; k++) acc[i][j][k] = 0.f;

    uint4 pf[8];
    const int nch = K >> 5;

#pragma unroll
    for (int j = 0; j < 2; j++) {
        pf[j]     = *(const uint4*)(Ahi + aoffs[j]);
        pf[2 + j] = *(const uint4*)(Alo + aoffs[j]);
        pf[4 + j] = *(const uint4*)(Bhi + boffs[j]);
        pf[6 + j] = *(const uint4*)(Blo + boffs[j]);
    }

    for (int c = 0; c < nch; c++) {
#pragma unroll
        for (int j = 0; j < 2; j++) {
            uint32_t so = (uint32_t)(lrow[j] * RS + lc4[j] * 8);
            *(uint4*)(sAh + so) = pf[j];
            *(uint4*)(sAl + so) = pf[2 + j];
            *(uint4*)(sBh + so) = pf[4 + j];
            *(uint4*)(sBl + so) = pf[6 + j];
        }
        __syncthreads();

        if (c + 1 < nch) {
            size_t kadv = (size_t)(c + 1) * 32;
#pragma unroll
            for (int j = 0; j < 2; j++) {
                pf[j]     = *(const uint4*)(Ahi + aoffs[j] + kadv);
                pf[2 + j] = *(const uint4*)(Alo + aoffs[j] + kadv);
                pf[4 + j] = *(const uint4*)(Bhi + boffs[j] + kadv);
                pf[6 + j] = *(const uint4*)(Blo + boffs[j] + kadv);
            }
        }

#pragma unroll
        for (int ks = 0; ks < 2; ks++) {
            const uint32_t kb = (uint32_t)(ks * 16 * 2);
            uint32_t ah[4][4], al[4][4], bh[2][4], bl[2][4];
#pragma unroll
            for (int mt = 0; mt < 4; mt++) {
                uint32_t off = (uint32_t)(mt * 16 * RS * 2) + kb;
                ldsm4(ah[mt], bAh + off);
                ldsm4(al[mt], bAl + off);
            }
#pragma unroll
            for (int p = 0; p < 2; p++) {
                uint32_t off = (uint32_t)(p * 16 * RS * 2) + kb;
                ldsm4(bh[p], bBh + off);
                ldsm4(bl[p], bBl + off);
            }
#pragma unroll
            for (int mt = 0; mt < 4; mt++)
#pragma unroll
                for (int nt = 0; nt < 4; nt++) {
                    const int p = nt >> 1, o = (nt & 1) * 2;
                    mma16816(acc[mt][nt], ah[mt], bh[p][o], bh[p][o + 1]);
                    mma16816(acc[mt][nt], ah[mt], bl[p][o], bl[p][o + 1]);
                    mma16816(acc[mt][nt], al[mt], bh[p][o], bh[p][o + 1]);
                }
        }
        __syncthreads();
    }

#pragma unroll
    for (int mt = 0; mt < 4; mt++) {
        int r0 = bm + wm + mt * 16 + (lane >> 2);
#pragma unroll
        for (int nt = 0; nt < 4; nt++) {
            int col = bn + wn + nt * 8 + (lane & 3) * 2;
            if (r0 < M)
                *(float2*)(C + (size_t)r0 * Nn + col) =
                    make_float2(acc[mt][nt][0], acc[mt][nt][1]);
            if (r0 + 8 < M)
                *(float2*)(C + (size_t)(r0 + 8) * Nn + col) =
                    make_float2(acc[mt][nt][2], acc[mt][nt][3]);
        }
    }
}

// ---------------- per-(node,head) attention coefficients e_src/e_dst ---------
template <int C>
__global__ void k_edot(const float* __restrict__ h, const float* __restrict__ as_,
                       const float* __restrict__ ad_, float* __restrict__ es,
                       float* __restrict__ ed) {
    int gt = blockIdx.x * blockDim.x + threadIdx.x;
    int w = gt >> 5, lane = gt & 31;
    if (w >= NN * 2) return;
    int node = w >> 1, head = w & 1;
    const float* hr = h + (size_t)node * (2 * C) + head * C;
    const float* ar = as_ + head * C;
    const float* dr = ad_ + head * C;
    float s1 = 0.f, s2 = 0.f;
#pragma unroll
    for (int c = lane * 4; c < C; c += 128) {
        float4 hv = *(const float4*)(hr + c);
        float4 av = *(const float4*)(ar + c);
        float4 dv = *(const float4*)(dr + c);
        s1 += hv.x * av.x + hv.y * av.y + hv.z * av.z + hv.w * av.w;
        s2 += hv.x * dv.x + hv.y * dv.y + hv.z * dv.z + hv.w * dv.w;
    }
#pragma unroll
    for (int o = 16; o; o >>= 1) {
        s1 += __shfl_xor_sync(0xffffffffu, s1, o);
        s2 += __shfl_xor_sync(0xffffffffu, s2, o);
    }
    if (lane == 0) { es[w] = s1; ed[w] = s2; }
}

// ---------------- fused attention aggregate + bias + BN(eval) + ReLU ---------
// ONE WARP PER NODE, both heads together. Depth-2 edge pipeline in pass B.
// STRIPED feature layout: lane owns float4 blocks {q*128 + lane*4} per head.
template <int C>
__global__ void k_att(const float* __restrict__ h, const float* __restrict__ es,
                      const float* __restrict__ ed, const float* __restrict__ bb,
                      const float* __restrict__ gg, const float* __restrict__ be,
                      const float* __restrict__ rm, const float* __restrict__ rv,
                      float* __restrict__ outp, bf16* __restrict__ ohi,
                      bf16* __restrict__ olo) {
    constexpr int VEC = C / 32;        // floats per lane per head (4 or 8)
    constexpr int NF4 = VEC / 4;       // float4s per lane per head (1 or 2)
    int gt = blockIdx.x * blockDim.x + threadIdx.x;
    int node = gt >> 5, lane = gt & 31;
    if (node >= NN) return;
    int beg = g_off[node], end = g_off[node + 1];
    float edv0 = ed[node * 2], edv1 = ed[node * 2 + 1];

    // pass A: both heads' leaky logits per edge; stash interleaved; track maxes
    float m0 = -1e30f, m1 = -1e30f;
    for (int j = beg + lane; j < end; j += 32) {
        int s = g_csr[j];
        float2 esv = *(const float2*)(es + 2 * s);
        float e0 = esv.x + edv0; e0 = e0 > 0.f ? e0 : 0.2f * e0;
        float e1 = esv.y + edv1; e1 = e1 > 0.f ? e1 : 0.2f * e1;
        *(float2*)(g_ew + 2 * (size_t)j) = make_float2(e0, e1);
        m0 = fmaxf(m0, e0);
        m1 = fmaxf(m1, e1);
    }
#pragma unroll
    for (int o = 16; o; o >>= 1) {
        m0 = fmaxf(m0, __shfl_xor_sync(0xffffffffu, m0, o));
        m1 = fmaxf(m1, __shfl_xor_sync(0xffffffffu, m1, o));
    }

    // pass B: weighted feature accumulation, both heads, depth-2 pipeline
    float acc0[VEC], acc1[VEC];
#pragma unroll
    for (int q = 0; q < VEC; q++) { acc0[q] = 0.f; acc1[q] = 0.f; }
    float ws0 = 0.f, ws1 = 0.f;

    for (int j0 = beg; j0 < end; j0 += 32) {
        int jj = j0 + lane;
        bool val = jj < end;
        int sl = val ? g_csr[jj] : 0;
        float wl0 = 0.f, wl1 = 0.f;
        if (val) {
            float2 e2 = *(const float2*)(g_ew + 2 * (size_t)jj);
            wl0 = __expf(e2.x - m0);
            wl1 = __expf(e2.y - m1);
        }
        ws0 += wl0; ws1 += wl1;
        int cnt = end - j0; if (cnt > 32) cnt = 32;

        float4 cur[2 * NF4], nxt[2 * NF4];
        float w0c, w1c;
        {
            int sv = __shfl_sync(0xffffffffu, sl, 0);
            w0c    = __shfl_sync(0xffffffffu, wl0, 0);
            w1c    = __shfl_sync(0xffffffffu, wl1, 0);
            const float4* p = (const float4*)(h + (size_t)sv * (2 * C));
#pragma unroll
            for (int q = 0; q < NF4; q++) {
                cur[q]       = __ldg(p + q * 32 + lane);             // head 0
                cur[NF4 + q] = __ldg(p + (C / 4) + q * 32 + lane);   // head 1
            }
        }
        for (int t = 0; t < cnt; t++) {
            float w0n = 0.f, w1n = 0.f;
            if (t + 1 < cnt) {
                int sv = __shfl_sync(0xffffffffu, sl, t + 1);
                w0n    = __shfl_sync(0xffffffffu, wl0, t + 1);
                w1n    = __shfl_sync(0xffffffffu, wl1, t + 1);
                const float4* p = (const float4*)(h + (size_t)sv * (2 * C));
#pragma unroll
                for (int q = 0; q < NF4; q++) {
                    nxt[q]       = __ldg(p + q * 32 + lane);
                    nxt[NF4 + q] = __ldg(p + (C / 4) + q * 32 + lane);
                }
            }
#pragma unroll
            for (int q = 0; q < NF4; q++) {
                acc0[4 * q + 0] += w0c * cur[q].x;
                acc0[4 * q + 1] += w0c * cur[q].y;
                acc0[4 * q + 2] += w0c * cur[q].z;
                acc0[4 * q + 3] += w0c * cur[q].w;
                acc1[4 * q + 0] += w1c * cur[NF4 + q].x;
                acc1[4 * q + 1] += w1c * cur[NF4 + q].y;
                acc1[4 * q + 2] += w1c * cur[NF4 + q].z;
                acc1[4 * q + 3] += w1c * cur[NF4 + q].w;
            }
#pragma unroll
            for (int q = 0; q < 2 * NF4; q++) cur[q] = nxt[q];
            w0c = w0n; w1c = w1n;
        }
    }
#pragma unroll
    for (int o = 16; o; o >>= 1) {
        ws0 += __shfl_xor_sync(0xffffffffu, ws0, o);
        ws1 += __shfl_xor_sync(0xffffffffu, ws1, o);
    }
    float inv0 = 1.0f / (ws0 + 1e-16f);
    float inv1 = 1.0f / (ws1 + 1e-16f);

    // epilogue per head: STRIPED mapping — acc[4q+i] is feature hd*C + q*128 + lane*4 + i
#pragma unroll
    for (int hd = 0; hd < 2; hd++) {
        const float* av = hd ? acc1 : acc0;
        float inv = hd ? inv1 : inv0;
#pragma unroll
        for (int q = 0; q < NF4; q++) {
            int f0 = hd * C + q * 128 + lane * 4;   // feature index of av[4q]
            float res[4];
#pragma unroll
            for (int k = 0; k < 4; k++) {
                int f = f0 + k;
                float o = av[4 * q + k] * inv + bb[f];
                o = (o - rm[f]) * rsqrtf(rv[f] + 1e-5f) * gg[f] + be[f];
                res[k] = fmaxf(o, 0.f);
            }
            if (C == 128) {
                size_t idx = (size_t)node * (2 * C) + f0;
                bf16 h0 = __float2bfloat16(res[0]);
                bf16 h1 = __float2bfloat16(res[1]);
                bf16 h2 = __float2bfloat16(res[2]);
                bf16 h3 = __float2bfloat16(res[3]);
                __nv_bfloat162* ph = (__nv_bfloat162*)(ohi + idx);
                ph[0] = __nv_bfloat162(h0, h1);
                ph[1] = __nv_bfloat162(h2, h3);
                __nv_bfloat162* pl = (__nv_bfloat162*)(olo + idx);
                pl[0] = __nv_bfloat162(__float2bfloat16(res[0] - __bfloat162float(h0)),
                                       __float2bfloat16(res[1] - __bfloat162float(h1)));
                pl[1] = __nv_bfloat162(__float2bfloat16(res[2] - __bfloat162float(h2)),
                                       __float2bfloat16(res[3] - __bfloat162float(h3)));
            } else {
                *(float4*)(outp + (size_t)node * (2 * C) + f0) =
                    make_float4(res[0], res[1], res[2], res[3]);
            }
        }
    }
}

// ---------------- launch -----------------------------------------------------
extern "C" void kernel_launch(void* const* d_in, const int* in_sizes, int n_in,
                              void* d_out, int out_size) {
    const float* x   = (const float*)d_in[0];
    const int*   ei  = (const int*)d_in[1];
    const float* W1  = (const float*)d_in[2];
    const float* as1 = (const float*)d_in[3];
    const float* ad1 = (const float*)d_in[4];
    const float* b1  = (const float*)d_in[5];
    const float* g1  = (const float*)d_in[6];
    const float* be1 = (const float*)d_in[7];
    const float* m1  = (const float*)d_in[8];
    const float* v1  = (const float*)d_in[9];
    const float* W2  = (const float*)d_in[10];
    const float* as2 = (const float*)d_in[11];
    const float* ad2 = (const float*)d_in[12];
    const float* b2  = (const float*)d_in[13];
    const float* g2  = (const float*)d_in[14];
    const float* be2 = (const float*)d_in[15];
    const float* m2  = (const float*)d_in[16];
    const float* v2  = (const float*)d_in[17];
    float* out = (float*)d_out;

    const int* srcp = ei;
    const int* dstp = ei + NE;

    float *h1, *h2;
    cudaGetSymbolAddress((void**)&h1, g_h1);
    cudaGetSymbolAddress((void**)&h2, g_h2);
    bf16 *xhi, *xlo, *f1hi, *f1lo, *w1hi, *w1lo, *w2hi, *w2lo;
    cudaGetSymbolAddress((void**)&xhi, g_xhi);
    cudaGetSymbolAddress((void**)&xlo, g_xlo);
    cudaGetSymbolAddress((void**)&f1hi, g_f1hi);
    cudaGetSymbolAddress((void**)&f1lo, g_f1lo);
    cudaGetSymbolAddress((void**)&w1hi, g_w1hi);
    cudaGetSymbolAddress((void**)&w1lo, g_w1lo);
    cudaGetSymbolAddress((void**)&w2hi, g_w2hi);
    cudaGetSymbolAddress((void**)&w2lo, g_w2lo);
    float *es1, *ed1, *es2, *ed2;
    cudaGetSymbolAddress((void**)&es1, g_es1);
    cudaGetSymbolAddress((void**)&ed1, g_ed1);
    cudaGetSymbolAddress((void**)&es2, g_es2);
    cudaGetSymbolAddress((void**)&ed2, g_ed2);

    const int edotBlocks = (NN * 2 * 32) / 256;   // 12500 (warp per node-head)
    const int attBlocks  = (NN + 7) / 8;          // 6250  (warp per node)
    const int mTiles = (NN + 127) / 128;          // 391

    // launches 0..2: conversions (k_split also zeroes g_deg)
    k_splitT<<<(128 * 256 + 255) / 256, 256>>>(W1, w1hi, w1lo, 128, 256);
    k_splitT<<<(256 * 512 + 255) / 256, 256>>>(W2, w2hi, w2lo, 256, 512);
    k_split<<<(NN * 128 + 255) / 256, 256>>>(x, xhi, xlo, NN * 128);

    // launch 3: layer-1 GEMM (ncu -s 5 -c 1 lands here)
    k_mma<<<dim3(2, mTiles), 256>>>(xhi, xlo, w1hi, w1lo, h1, NN, 256, 128);

    // CSR build
    k_hist<<<(NET + 255) / 256, 256>>>(dstp);
    k_scan<<<1, 1024>>>();
    k_fill<<<(NET + 255) / 256, 256>>>(srcp, dstp);

    // layer 1 attention
    k_edot<128><<<edotBlocks, 256>>>(h1, as1, ad1, es1, ed1);
    k_att<128><<<attBlocks, 256>>>(h1, es1, ed1, b1, g1, be1, m1, v1, nullptr, f1hi, f1lo);

    // layer 2
    k_mma<<<dim3(4, mTiles), 256>>>(f1hi, f1lo, w2hi, w2lo, h2, NN, 512, 256);
    k_edot<256><<<edotBlocks, 256>>>(h2, as2, ad2, es2, ed2);
    k_att<256><<<attBlocks, 256>>>(h2, es2, ed2, b2, g2, be2, m2, v2, out, nullptr, nullptr);
}

// round 9
// speedup vs baseline: 1.0226x; 1.0226x over previous
#include <cuda_runtime.h>
#include <cuda_bf16.h>
#include <cstdint>

#define NN  50000
#define NE  800000
#define NET 850000   // NE + NN self loops

typedef __nv_bfloat16 bf16;

// ---------------- scratch (static device globals; no allocs allowed) ----------
__device__ float g_h1[(size_t)NN * 256];   // x @ W1 (f32, gather source)
__device__ float g_h2[(size_t)NN * 512];   // f1 @ W2 (f32, gather source)
__device__ bf16  g_xhi[(size_t)NN * 128], g_xlo[(size_t)NN * 128];
__device__ bf16  g_f1hi[(size_t)NN * 256], g_f1lo[(size_t)NN * 256];
__device__ bf16  g_w1hi[256 * 128], g_w1lo[256 * 128];     // W1^T [N=256,K=128]
__device__ bf16  g_w2hi[512 * 256], g_w2lo[512 * 256];     // W2^T [N=512,K=256]
__device__ float g_es1[NN * 2], g_ed1[NN * 2];
__device__ float g_es2[NN * 2], g_ed2[NN * 2];
__device__ float g_ew[(size_t)2 * NET];    // per-(head,edge) leaky logits
__device__ int   g_deg[NN];
__device__ int   g_off[NN + 1];
__device__ int   g_cur[NN];
__device__ int   g_csr[NET];               // src per CSR slot (grouped by dst)

// ---------------- PTX helpers (arch-generic: ldmatrix + mma.sync) -------------
__device__ __forceinline__ uint32_t s2u(const void* p) {
    uint32_t a;
    asm("{ .reg .u64 t; cvta.to.shared.u64 t, %1; cvt.u32.u64 %0, t; }"
        : "=r"(a) : "l"(p));
    return a;
}

__device__ __forceinline__ void ldsm4(uint32_t* r, uint32_t addr) {
    asm volatile("ldmatrix.sync.aligned.m8n8.x4.shared.b16 {%0,%1,%2,%3}, [%4];"
                 : "=r"(r[0]), "=r"(r[1]), "=r"(r[2]), "=r"(r[3]) : "r"(addr));
}

__device__ __forceinline__ void mma16816(float* d, const uint32_t* a,
                                         uint32_t b0, uint32_t b1) {
    asm volatile(
        "mma.sync.aligned.m16n8k16.row.col.f32.bf16.bf16.f32 "
        "{%0,%1,%2,%3}, {%4,%5,%6,%7}, {%8,%9}, {%0,%1,%2,%3};"
        : "+f"(d[0]), "+f"(d[1]), "+f"(d[2]), "+f"(d[3])
        : "r"(a[0]), "r"(a[1]), "r"(a[2]), "r"(a[3]), "r"(b0), "r"(b1));
}

// ---------------- fp32 -> bf16 hi/lo split (+fused g_deg zero) ----------------
__global__ void k_split(const float* __restrict__ in, bf16* __restrict__ hi,
                        bf16* __restrict__ lo, int n) {
    int i = blockIdx.x * blockDim.x + threadIdx.x;
    if (i < NN) g_deg[i] = 0;
    if (i >= n) return;
    float v = in[i];
    bf16 h = __float2bfloat16(v);
    hi[i] = h;
    lo[i] = __float2bfloat16(v - __bfloat162float(h));
}

// W[K,N] row-major -> Wt[N,K] hi/lo split
__global__ void k_splitT(const float* __restrict__ W, bf16* __restrict__ hiT,
                         bf16* __restrict__ loT, int K, int N) {
    int i = blockIdx.x * blockDim.x + threadIdx.x;
    if (i >= K * N) return;
    int k = i / N, n = i % N;
    float v = W[i];
    bf16 h = __float2bfloat16(v);
    hiT[(size_t)n * K + k] = h;
    loT[(size_t)n * K + k] = __float2bfloat16(v - __bfloat162float(h));
}

// ---------------- CSR build (proven versions) ---------------------------------
__global__ void k_hist(const int* __restrict__ dst) {
    int i = blockIdx.x * blockDim.x + threadIdx.x;
    if (i >= NET) return;
    int d = (i < NE) ? dst[i] : (i - NE);
    atomicAdd(&g_deg[d], 1);
}

__global__ void k_scan() {
    __shared__ int sums[1024];
    const int t  = threadIdx.x;
    const int CH = (NN + 1023) / 1024;
    int b = t * CH, e = b + CH; if (e > NN) e = NN; if (b > NN) b = NN;
    int s = 0;
    for (int i = b; i < e; i++) s += g_deg[i];
    sums[t] = s;
    __syncthreads();
    for (int off = 1; off < 1024; off <<= 1) {
        int v = (t >= off) ? sums[t - off] : 0;
        __syncthreads();
        sums[t] += v;
        __syncthreads();
    }
    int pre = (t == 0) ? 0 : sums[t - 1];
    for (int i = b; i < e; i++) {
        g_off[i] = pre;
        g_cur[i] = pre;
        pre += g_deg[i];
    }
    if (t == 1023) g_off[NN] = NET;
}

__global__ void k_fill(const int* __restrict__ src, const int* __restrict__ dst) {
    int i = blockIdx.x * blockDim.x + threadIdx.x;
    if (i >= NET) return;
    int s, d;
    if (i < NE) { s = src[i]; d = dst[i]; }
    else        { s = d = i - NE; }
    int pos = atomicAdd(&g_cur[d], 1);
    g_csr[pos] = s;
}

// ---------------- HMMA GEMM v2: C[M,Nn] = A[M,K] @ Wt[Nn,K]^T -----------------
// bf16 split: C = Ahi*Bhi + Ahi*Blo + Alo*Bhi (fp32 acc), fp32 output.
// 512 threads, 128x128 tile, 16 warps (4x4), warp tile 32x32.
// DOUBLE-BUFFERED dynamic smem (2 x 40KB), ONE sync per K-chunk.
#define RS 40          // smem row stride in bf16 (80B, ldmatrix conflict-free)
#define BUFB 40960     // bytes per buffer (4 arrays x 128*RS*2)
#define ARRB 10240     // bytes per array

__global__ __launch_bounds__(512)
void k_mma(const bf16* __restrict__ Ahi, const bf16* __restrict__ Alo,
           const bf16* __restrict__ Bhi, const bf16* __restrict__ Blo,
           float* __restrict__ C, int M, int Nn, int K) {
    extern __shared__ __align__(16) char smem[];

    const int tid = threadIdx.x, lane = tid & 31, wid = tid >> 5;
    const int bm = blockIdx.y * 128, bn = blockIdx.x * 128;
    const int wm = (wid & 3) * 32;
    const int wn = (wid >> 2) * 32;

    // gmem loader: 1 uint4 per array per chunk: 128 rows x 32 cols
    const int lrow = tid >> 2, lc4 = tid & 3;
    int ra = bm + lrow; if (ra >= M) ra = M - 1;
    const size_t aoff = (size_t)ra * K + lc4 * 8;
    const size_t boff = (size_t)(bn + lrow) * K + lc4 * 8;
    const uint32_t soB = (uint32_t)((lrow * RS + lc4 * 8) * 2);   // byte offset

    // ldmatrix per-lane base byte offsets within an array
    const int li = lane >> 3, l8 = lane & 7;
    const uint32_t aA = (uint32_t)(((wm + (li & 1) * 8 + l8) * RS + (li >> 1) * 8) * 2);
    const uint32_t aB = (uint32_t)(((wn + (li >> 1) * 8 + l8) * RS + (li & 1) * 8) * 2);
    const uint32_t base = s2u(smem);

    float acc[2][4][4];
#pragma unroll
    for (int i = 0; i < 2; i++)
#pragma unroll
        for (int j = 0; j < 4; j++)
#pragma unroll
            for (int k = 0; k < 4; k++) acc[i][j][k] = 0.f;

    uint4 pf[4];
    const int nch = K >> 5;

    pf[0] = *(const uint4*)(Ahi + aoff);
    pf[1] = *(const uint4*)(Alo + aoff);
    pf[2] = *(const uint4*)(Bhi + boff);
    pf[3] = *(const uint4*)(Blo + boff);

    for (int c = 0; c < nch; c++) {
        const uint32_t bufo = (uint32_t)((c & 1) * BUFB);
        char* pb = smem + bufo;
        *(uint4*)(pb + soB)            = pf[0];
        *(uint4*)(pb + ARRB + soB)     = pf[1];
        *(uint4*)(pb + 2 * ARRB + soB) = pf[2];
        *(uint4*)(pb + 3 * ARRB + soB) = pf[3];
        __syncthreads();

        if (c + 1 < nch) {
            size_t kadv = (size_t)(c + 1) * 32;
            pf[0] = *(const uint4*)(Ahi + aoff + kadv);
            pf[1] = *(const uint4*)(Alo + aoff + kadv);
            pf[2] = *(const uint4*)(Bhi + boff + kadv);
            pf[3] = *(const uint4*)(Blo + boff + kadv);
        }

        const uint32_t bAh = base + bufo + aA;
        const uint32_t bAl = base + bufo + ARRB + aA;
        const uint32_t bBh = base + bufo + 2 * ARRB + aB;
        const uint32_t bBl = base + bufo + 3 * ARRB + aB;

#pragma unroll
        for (int ks = 0; ks < 2; ks++) {
            const uint32_t kb = (uint32_t)(ks * 16 * 2);
            uint32_t ah[2][4], al[2][4], bh[2][4], bl[2][4];
#pragma unroll
            for (int mt = 0; mt < 2; mt++) {
                uint32_t off = (uint32_t)(mt * 16 * RS * 2) + kb;
                ldsm4(ah[mt], bAh + off);
                ldsm4(al[mt], bAl + off);
            }
#pragma unroll
            for (int p = 0; p < 2; p++) {
                uint32_t off = (uint32_t)(p * 16 * RS * 2) + kb;
                ldsm4(bh[p], bBh + off);
                ldsm4(bl[p], bBl + off);
            }
#pragma unroll
            for (int mt = 0; mt < 2; mt++)
#pragma unroll
                for (int nt = 0; nt < 4; nt++) {
                    const int p = nt >> 1, o = (nt & 1) * 2;
                    mma16816(acc[mt][nt], ah[mt], bh[p][o], bh[p][o + 1]);
                    mma16816(acc[mt][nt], ah[mt], bl[p][o], bl[p][o + 1]);
                    mma16816(acc[mt][nt], al[mt], bh[p][o], bh[p][o + 1]);
                }
        }
        // no trailing sync: next iteration writes the OTHER buffer
    }

#pragma unroll
    for (int mt = 0; mt < 2; mt++) {
        int r0 = bm + wm + mt * 16 + (lane >> 2);
#pragma unroll
        for (int nt = 0; nt < 4; nt++) {
            int col = bn + wn + nt * 8 + (lane & 3) * 2;
            if (r0 < M)
                *(float2*)(C + (size_t)r0 * Nn + col) =
                    make_float2(acc[mt][nt][0], acc[mt][nt][1]);
            if (r0 + 8 < M)
                *(float2*)(C + (size_t)(r0 + 8) * Nn + col) =
                    make_float2(acc[mt][nt][2], acc[mt][nt][3]);
        }
    }
}

// ---------------- per-(node,head) attention coefficients e_src/e_dst ---------
template <int C>
__global__ void k_edot(const float* __restrict__ h, const float* __restrict__ as_,
                       const float* __restrict__ ad_, float* __restrict__ es,
                       float* __restrict__ ed) {
    int gt = blockIdx.x * blockDim.x + threadIdx.x;
    int w = gt >> 5, lane = gt & 31;
    if (w >= NN * 2) return;
    int node = w >> 1, head = w & 1;
    const float* hr = h + (size_t)node * (2 * C) + head * C;
    const float* ar = as_ + head * C;
    const float* dr = ad_ + head * C;
    float s1 = 0.f, s2 = 0.f;
#pragma unroll
    for (int c = lane * 4; c < C; c += 128) {
        float4 hv = *(const float4*)(hr + c);
        float4 av = *(const float4*)(ar + c);
        float4 dv = *(const float4*)(dr + c);
        s1 += hv.x * av.x + hv.y * av.y + hv.z * av.z + hv.w * av.w;
        s2 += hv.x * dv.x + hv.y * dv.y + hv.z * dv.z + hv.w * dv.w;
    }
#pragma unroll
    for (int o = 16; o; o >>= 1) {
        s1 += __shfl_xor_sync(0xffffffffu, s1, o);
        s2 += __shfl_xor_sync(0xffffffffu, s2, o);
    }
    if (lane == 0) { es[w] = s1; ed[w] = s2; }
}

// ---------------- fused attention aggregate + bias + BN(eval) + ReLU ---------
// one warp per (node, head); pass A stashes leaky logits to g_ew (per-lane
// read-back, no cross-thread dependency); pass B reads them coalesced.
// (round-6 proven version, 600us)
template <int C>
__global__ void k_att(const float* __restrict__ h, const float* __restrict__ es,
                      const float* __restrict__ ed, const float* __restrict__ bb,
                      const float* __restrict__ gg, const float* __restrict__ be,
                      const float* __restrict__ rm, const float* __restrict__ rv,
                      float* __restrict__ outp, bf16* __restrict__ ohi,
                      bf16* __restrict__ olo) {
    int gt = blockIdx.x * blockDim.x + threadIdx.x;
    int w = gt >> 5, lane = gt & 31;
    if (w >= NN * 2) return;
    int node = w >> 1, head = w & 1;
    int beg = g_off[node], end = g_off[node + 1];
    float edv = ed[node * 2 + head];
    float* ew = g_ew + (size_t)head * NET;

    // pass A: compute + stash leaky logits, track max
    float m = -1e30f;
    for (int j = beg + lane; j < end; j += 32) {
        int s = g_csr[j];
        float e = es[s * 2 + head] + edv;
        e = e > 0.f ? e : 0.2f * e;
        ew[j] = e;
        m = fmaxf(m, e);
    }
#pragma unroll
    for (int o = 16; o; o >>= 1) m = fmaxf(m, __shfl_xor_sync(0xffffffffu, m, o));

    // pass B: weighted feature accumulation
    float4 acc0 = make_float4(0.f, 0.f, 0.f, 0.f);
    float4 acc1 = make_float4(0.f, 0.f, 0.f, 0.f);
    float wsum = 0.f;
    for (int j0 = beg; j0 < end; j0 += 32) {
        int jj = j0 + lane;
        bool val = jj < end;
        int sl = val ? g_csr[jj] : 0;
        float wl = val ? __expf(ew[jj] - m) : 0.f;
        wsum += wl;
        int cnt = end - j0; if (cnt > 32) cnt = 32;
        for (int t = 0; t < cnt; t++) {
            float wv = __shfl_sync(0xffffffffu, wl, t);
            int   sv = __shfl_sync(0xffffffffu, sl, t);
            const float4* p = (const float4*)(h + (size_t)sv * (2 * C) + head * C) + lane;
            float4 v = __ldg(p);
            acc0.x += wv * v.x; acc0.y += wv * v.y;
            acc0.z += wv * v.z; acc0.w += wv * v.w;
            if (C == 256) {
                float4 v2 = __ldg(p + 32);
                acc1.x += wv * v2.x; acc1.y += wv * v2.y;
                acc1.z += wv * v2.z; acc1.w += wv * v2.w;
            }
        }
    }
#pragma unroll
    for (int o = 16; o; o >>= 1) wsum += __shfl_xor_sync(0xffffffffu, wsum, o);
    float inv = 1.0f / (wsum + 1e-16f);

    // epilogue: alpha-normalize, +bias, BN eval, ReLU (striped for C=256)
    int f0 = head * C + lane * 4;
    float res0[4];
    {
        float vals[4] = {acc0.x, acc0.y, acc0.z, acc0.w};
#pragma unroll
        for (int k = 0; k < 4; k++) {
            int f = f0 + k;
            float o = vals[k] * inv + bb[f];
            o = (o - rm[f]) * rsqrtf(rv[f] + 1e-5f) * gg[f] + be[f];
            res0[k] = fmaxf(o, 0.f);
        }
    }
    if (C == 128) {
        size_t idx = (size_t)node * (2 * C) + f0;
        bf16 h0 = __float2bfloat16(res0[0]);
        bf16 h1 = __float2bfloat16(res0[1]);
        bf16 h2 = __float2bfloat16(res0[2]);
        bf16 h3 = __float2bfloat16(res0[3]);
        __nv_bfloat162* ph = (__nv_bfloat162*)(ohi + idx);
        ph[0] = __nv_bfloat162(h0, h1);
        ph[1] = __nv_bfloat162(h2, h3);
        __nv_bfloat162* pl = (__nv_bfloat162*)(olo + idx);
        pl[0] = __nv_bfloat162(__float2bfloat16(res0[0] - __bfloat162float(h0)),
                               __float2bfloat16(res0[1] - __bfloat162float(h1)));
        pl[1] = __nv_bfloat162(__float2bfloat16(res0[2] - __bfloat162float(h2)),
                               __float2bfloat16(res0[3] - __bfloat162float(h3)));
    } else {
        *(float4*)(outp + (size_t)node * (2 * C) + f0) =
            make_float4(res0[0], res0[1], res0[2], res0[3]);
        int f1 = f0 + 128;
        float vals[4] = {acc1.x, acc1.y, acc1.z, acc1.w};
        float4 o4;
        float* ov = (float*)&o4;
#pragma unroll
        for (int k = 0; k < 4; k++) {
            int f = f1 + k;
            float o = vals[k] * inv + bb[f];
            o = (o - rm[f]) * rsqrtf(rv[f] + 1e-5f) * gg[f] + be[f];
            ov[k] = fmaxf(o, 0.f);
        }
        *(float4*)(outp + (size_t)node * (2 * C) + f1) = o4;
    }
}

// ---------------- launch -----------------------------------------------------
extern "C" void kernel_launch(void* const* d_in, const int* in_sizes, int n_in,
                              void* d_out, int out_size) {
    const float* x   = (const float*)d_in[0];
    const int*   ei  = (const int*)d_in[1];
    const float* W1  = (const float*)d_in[2];
    const float* as1 = (const float*)d_in[3];
    const float* ad1 = (const float*)d_in[4];
    const float* b1  = (const float*)d_in[5];
    const float* g1  = (const float*)d_in[6];
    const float* be1 = (const float*)d_in[7];
    const float* m1  = (const float*)d_in[8];
    const float* v1  = (const float*)d_in[9];
    const float* W2  = (const float*)d_in[10];
    const float* as2 = (const float*)d_in[11];
    const float* ad2 = (const float*)d_in[12];
    const float* b2  = (const float*)d_in[13];
    const float* g2  = (const float*)d_in[14];
    const float* be2 = (const float*)d_in[15];
    const float* m2  = (const float*)d_in[16];
    const float* v2  = (const float*)d_in[17];
    float* out = (float*)d_out;

    const int* srcp = ei;
    const int* dstp = ei + NE;

    float *h1, *h2;
    cudaGetSymbolAddress((void**)&h1, g_h1);
    cudaGetSymbolAddress((void**)&h2, g_h2);
    bf16 *xhi, *xlo, *f1hi, *f1lo, *w1hi, *w1lo, *w2hi, *w2lo;
    cudaGetSymbolAddress((void**)&xhi, g_xhi);
    cudaGetSymbolAddress((void**)&xlo, g_xlo);
    cudaGetSymbolAddress((void**)&f1hi, g_f1hi);
    cudaGetSymbolAddress((void**)&f1lo, g_f1lo);
    cudaGetSymbolAddress((void**)&w1hi, g_w1hi);
    cudaGetSymbolAddress((void**)&w1lo, g_w1lo);
    cudaGetSymbolAddress((void**)&w2hi, g_w2hi);
    cudaGetSymbolAddress((void**)&w2lo, g_w2lo);
    float *es1, *ed1, *es2, *ed2;
    cudaGetSymbolAddress((void**)&es1, g_es1);
    cudaGetSymbolAddress((void**)&ed1, g_ed1);
    cudaGetSymbolAddress((void**)&es2, g_es2);
    cudaGetSymbolAddress((void**)&ed2, g_ed2);

    static bool attrSet = false;
    if (!attrSet) {
        cudaFuncSetAttribute(k_mma, cudaFuncAttributeMaxDynamicSharedMemorySize,
                             2 * BUFB);
        attrSet = true;
    }

    const int warpBlocks = (NN * 2 * 32) / 256;   // 12500 (warp per node-head)
    const int mTiles = (NN + 127) / 128;          // 391

    // launches 0..2: conversions (k_split also zeroes g_deg)
    k_splitT<<<(128 * 256 + 255) / 256, 256>>>(W1, w1hi, w1lo, 128, 256);
    k_splitT<<<(256 * 512 + 255) / 256, 256>>>(W2, w2hi, w2lo, 256, 512);
    k_split<<<(NN * 128 + 255) / 256, 256>>>(x, xhi, xlo, NN * 128);

    // launch 3: layer-1 GEMM (ncu -s 5 -c 1 lands here)
    k_mma<<<dim3(2, mTiles), 512, 2 * BUFB>>>(xhi, xlo, w1hi, w1lo, h1, NN, 256, 128);

    // CSR build
    k_hist<<<(NET + 255) / 256, 256>>>(dstp);
    k_scan<<<1, 1024>>>();
    k_fill<<<(NET + 255) / 256, 256>>>(srcp, dstp);

    // layer 1 attention
    k_edot<128><<<warpBlocks, 256>>>(h1, as1, ad1, es1, ed1);
    k_att<128><<<warpBlocks, 256>>>(h1, es1, ed1, b1, g1, be1, m1, v1, nullptr, f1hi, f1lo);

    // layer 2
    k_mma<<<dim3(4, mTiles), 512, 2 * BUFB>>>(f1hi, f1lo, w2hi, w2lo, h2, NN, 512, 256);
    k_edot<256><<<warpBlocks, 256>>>(h2, as2, ad2, es2, ed2);
    k_att<256><<<warpBlocks, 256>>>(h2, es2, ed2, b2, g2, be2, m2, v2, out, nullptr, nullptr);
}

// round 11
// speedup vs baseline: 1.0273x; 1.0046x over previous
#include <cuda_runtime.h>
#include <cuda_bf16.h>
#include <cstdint>

#define NN  50000
#define NE  800000
#define NET 850000   // NE + NN self loops

typedef __nv_bfloat16 bf16;

// ---------------- scratch (static device globals; no allocs allowed) ----------
__device__ float g_h1[(size_t)NN * 256];   // x @ W1 (f32, gather source)
__device__ float g_h2[(size_t)NN * 512];   // f1 @ W2 (f32, gather source)
__device__ bf16  g_xhi[(size_t)NN * 128], g_xlo[(size_t)NN * 128];
__device__ bf16  g_f1hi[(size_t)NN * 256], g_f1lo[(size_t)NN * 256];
__device__ bf16  g_w1hi[256 * 128], g_w1lo[256 * 128];     // W1^T [N=256,K=128]
__device__ bf16  g_w2hi[512 * 256], g_w2lo[512 * 256];     // W2^T [N=512,K=256]
__device__ float g_es1[NN * 2], g_ed1[NN * 2];
__device__ float g_es2[NN * 2], g_ed2[NN * 2];
__device__ float g_ew[(size_t)2 * NET];    // per-(head,edge) leaky logits
__device__ int   g_deg[NN];
__device__ int   g_off[NN + 1];
__device__ int   g_cur[NN];
__device__ int   g_csr[NET];               // src per CSR slot (grouped by dst)

// ---------------- PTX helpers (arch-generic: ldmatrix + mma.sync) -------------
__device__ __forceinline__ uint32_t s2u(const void* p) {
    uint32_t a;
    asm("{ .reg .u64 t; cvta.to.shared.u64 t, %1; cvt.u32.u64 %0, t; }"
        : "=r"(a) : "l"(p));
    return a;
}

__device__ __forceinline__ void ldsm4(uint32_t* r, uint32_t addr) {
    asm volatile("ldmatrix.sync.aligned.m8n8.x4.shared.b16 {%0,%1,%2,%3}, [%4];"
                 : "=r"(r[0]), "=r"(r[1]), "=r"(r[2]), "=r"(r[3]) : "r"(addr));
}

__device__ __forceinline__ void mma16816(float* d, const uint32_t* a,
                                         uint32_t b0, uint32_t b1) {
    asm volatile(
        "mma.sync.aligned.m16n8k16.row.col.f32.bf16.bf16.f32 "
        "{%0,%1,%2,%3}, {%4,%5,%6,%7}, {%8,%9}, {%0,%1,%2,%3};"
        : "+f"(d[0]), "+f"(d[1]), "+f"(d[2]), "+f"(d[3])
        : "r"(a[0]), "r"(a[1]), "r"(a[2]), "r"(a[3]), "r"(b0), "r"(b1));
}

// ---------------- fp32 -> bf16 hi/lo split (+fused g_deg zero) ----------------
__global__ void k_split(const float* __restrict__ in, bf16* __restrict__ hi,
                        bf16* __restrict__ lo, int n) {
    int i = blockIdx.x * blockDim.x + threadIdx.x;
    if (i < NN) g_deg[i] = 0;
    if (i >= n) return;
    float v = in[i];
    bf16 h = __float2bfloat16(v);
    hi[i] = h;
    lo[i] = __float2bfloat16(v - __bfloat162float(h));
}

// W[K,N] row-major -> Wt[N,K] hi/lo split
__global__ void k_splitT(const float* __restrict__ W, bf16* __restrict__ hiT,
                         bf16* __restrict__ loT, int K, int N) {
    int i = blockIdx.x * blockDim.x + threadIdx.x;
    if (i >= K * N) return;
    int k = i / N, n = i % N;
    float v = W[i];
    bf16 h = __float2bfloat16(v);
    hiT[(size_t)n * K + k] = h;
    loT[(size_t)n * K + k] = __float2bfloat16(v - __bfloat162float(h));
}

// ---------------- CSR build (proven versions) ---------------------------------
__global__ void k_hist(const int* __restrict__ dst) {
    int i = blockIdx.x * blockDim.x + threadIdx.x;
    if (i >= NET) return;
    int d = (i < NE) ? dst[i] : (i - NE);
    atomicAdd(&g_deg[d], 1);
}

__global__ void k_scan() {
    __shared__ int sums[1024];
    const int t  = threadIdx.x;
    const int CH = (NN + 1023) / 1024;
    int b = t * CH, e = b + CH; if (e > NN) e = NN; if (b > NN) b = NN;
    int s = 0;
    for (int i = b; i < e; i++) s += g_deg[i];
    sums[t] = s;
    __syncthreads();
    for (int off = 1; off < 1024; off <<= 1) {
        int v = (t >= off) ? sums[t - off] : 0;
        __syncthreads();
        sums[t] += v;
        __syncthreads();
    }
    int pre = (t == 0) ? 0 : sums[t - 1];
    for (int i = b; i < e; i++) {
        g_off[i] = pre;
        g_cur[i] = pre;
        pre += g_deg[i];
    }
    if (t == 1023) g_off[NN] = NET;
}

__global__ void k_fill(const int* __restrict__ src, const int* __restrict__ dst) {
    int i = blockIdx.x * blockDim.x + threadIdx.x;
    if (i >= NET) return;
    int s, d;
    if (i < NE) { s = src[i]; d = dst[i]; }
    else        { s = d = i - NE; }
    int pos = atomicAdd(&g_cur[d], 1);
    g_csr[pos] = s;
}

// ---------------- HMMA GEMM v3: C[M,Nn] = A[M,K] @ Wt[Nn,K]^T -----------------
// bf16 split: C = Ahi*Bhi + Ahi*Blo + Alo*Bhi (fp32 acc), fp32 output.
// 256 threads, 128x64 tile, 8 warps (4x2), warp tile 32x32.
// Double-buffered dynamic smem (2 x 30KB), one sync per chunk; 2 CTAs/SM.
#define RS 40              // smem row stride in bf16 (80B, conflict-free)
#define ARRA 10240         // A array bytes (128*RS*2)
#define ARRB2 5120         // B array bytes (64*RS*2)
#define BUFB (2*ARRA + 2*ARRB2)   // 30720 per buffer
#define OFF_AH 0
#define OFF_AL ARRA
#define OFF_BH (2*ARRA)
#define OFF_BL (2*ARRA + ARRB2)

__global__ __launch_bounds__(256)
void k_mma(const bf16* __restrict__ Ahi, const bf16* __restrict__ Alo,
           const bf16* __restrict__ Bhi, const bf16* __restrict__ Blo,
           float* __restrict__ C, int M, int Nn, int K) {
    extern __shared__ __align__(16) char smem[];

    const int tid = threadIdx.x, lane = tid & 31, wid = tid >> 5;
    const int bm = blockIdx.y * 128, bn = blockIdx.x * 64;
    const int wm = (wid & 3) * 32;
    const int wn = (wid >> 2) * 32;

    // gmem loaders.  A: 2 rounds x (hi,lo); rows 0..127, 32 cols per chunk.
    int arow[2];
    size_t aoff[2];
#pragma unroll
    for (int r = 0; r < 2; r++) {
        int idx = tid + r * 256;
        arow[r] = idx >> 2;
        int ra = bm + arow[r]; if (ra >= M) ra = M - 1;
        aoff[r] = (size_t)ra * K + (idx & 3) * 8;
    }
    // B: 1 round x (hi,lo); rows 0..63
    const int brow = tid >> 2;
    const size_t boff = (size_t)(bn + brow) * K + (tid & 3) * 8;

    const uint32_t soA0 = (uint32_t)((arow[0] * RS + (tid & 3) * 8) * 2);
    const uint32_t soA1 = (uint32_t)((arow[1] * RS + ((tid + 256) & 3) * 8) * 2);
    const uint32_t soB  = (uint32_t)((brow * RS + (tid & 3) * 8) * 2);

    // ldmatrix per-lane base byte offsets within arrays
    const int li = lane >> 3, l8 = lane & 7;
    const uint32_t aA = (uint32_t)(((wm + (li & 1) * 8 + l8) * RS + (li >> 1) * 8) * 2);
    const uint32_t aB = (uint32_t)(((wn + (li >> 1) * 8 + l8) * RS + (li & 1) * 8) * 2);
    const uint32_t base = s2u(smem);

    float acc[2][4][4];
#pragma unroll
    for (int i = 0; i < 2; i++)
#pragma unroll
        for (int j = 0; j < 4; j++)
#pragma unroll
            for (int k = 0; k < 4; k++) acc[i][j][k] = 0.f;

    uint4 pfA[2][2], pfB[2];
    const int nch = K >> 5;

#pragma unroll
    for (int r = 0; r < 2; r++) {
        pfA[0][r] = *(const uint4*)(Ahi + aoff[r]);
        pfA[1][r] = *(const uint4*)(Alo + aoff[r]);
    }
    pfB[0] = *(const uint4*)(Bhi + boff);
    pfB[1] = *(const uint4*)(Blo + boff);

    for (int c = 0; c < nch; c++) {
        const uint32_t bufo = (uint32_t)((c & 1) * BUFB);
        char* pb = smem + bufo;
        *(uint4*)(pb + OFF_AH + soA0) = pfA[0][0];
        *(uint4*)(pb + OFF_AH + soA1) = pfA[0][1];
        *(uint4*)(pb + OFF_AL + soA0) = pfA[1][0];
        *(uint4*)(pb + OFF_AL + soA1) = pfA[1][1];
        *(uint4*)(pb + OFF_BH + soB)  = pfB[0];
        *(uint4*)(pb + OFF_BL + soB)  = pfB[1];
        __syncthreads();

        if (c + 1 < nch) {
            size_t kadv = (size_t)(c + 1) * 32;
#pragma unroll
            for (int r = 0; r < 2; r++) {
                pfA[0][r] = *(const uint4*)(Ahi + aoff[r] + kadv);
                pfA[1][r] = *(const uint4*)(Alo + aoff[r] + kadv);
            }
            pfB[0] = *(const uint4*)(Bhi + boff + kadv);
            pfB[1] = *(const uint4*)(Blo + boff + kadv);
        }

        const uint32_t bAh = base + bufo + OFF_AH + aA;
        const uint32_t bAl = base + bufo + OFF_AL + aA;
        const uint32_t bBh = base + bufo + OFF_BH + aB;
        const uint32_t bBl = base + bufo + OFF_BL + aB;

#pragma unroll
        for (int ks = 0; ks < 2; ks++) {
            const uint32_t kb = (uint32_t)(ks * 16 * 2);
            uint32_t ah[2][4], al[2][4], bh[2][4], bl[2][4];
#pragma unroll
            for (int mt = 0; mt < 2; mt++) {
                uint32_t off = (uint32_t)(mt * 16 * RS * 2) + kb;
                ldsm4(ah[mt], bAh + off);
                ldsm4(al[mt], bAl + off);
            }
#pragma unroll
            for (int p = 0; p < 2; p++) {
                uint32_t off = (uint32_t)(p * 16 * RS * 2) + kb;
                ldsm4(bh[p], bBh + off);
                ldsm4(bl[p], bBl + off);
            }
#pragma unroll
            for (int mt = 0; mt < 2; mt++)
#pragma unroll
                for (int nt = 0; nt < 4; nt++) {
                    const int p = nt >> 1, o = (nt & 1) * 2;
                    mma16816(acc[mt][nt], ah[mt], bh[p][o], bh[p][o + 1]);
                    mma16816(acc[mt][nt], ah[mt], bl[p][o], bl[p][o + 1]);
                    mma16816(acc[mt][nt], al[mt], bh[p][o], bh[p][o + 1]);
                }
        }
        // no trailing sync: next iteration writes the OTHER buffer
    }

#pragma unroll
    for (int mt = 0; mt < 2; mt++) {
        int r0 = bm + wm + mt * 16 + (lane >> 2);
#pragma unroll
        for (int nt = 0; nt < 4; nt++) {
            int col = bn + wn + nt * 8 + (lane & 3) * 2;
            if (r0 < M)
                *(float2*)(C + (size_t)r0 * Nn + col) =
                    make_float2(acc[mt][nt][0], acc[mt][nt][1]);
            if (r0 + 8 < M)
                *(float2*)(C + (size_t)(r0 + 8) * Nn + col) =
                    make_float2(acc[mt][nt][2], acc[mt][nt][3]);
        }
    }
}

// ---------------- per-(node,head) attention coefficients e_src/e_dst ---------
template <int C>
__global__ void k_edot(const float* __restrict__ h, const float* __restrict__ as_,
                       const float* __restrict__ ad_, float* __restrict__ es,
                       float* __restrict__ ed) {
    int gt = blockIdx.x * blockDim.x + threadIdx.x;
    int w = gt >> 5, lane = gt & 31;
    if (w >= NN * 2) return;
    int node = w >> 1, head = w & 1;
    const float* hr = h + (size_t)node * (2 * C) + head * C;
    const float* ar = as_ + head * C;
    const float* dr = ad_ + head * C;
    float s1 = 0.f, s2 = 0.f;
#pragma unroll
    for (int c = lane * 4; c < C; c += 128) {
        float4 hv = *(const float4*)(hr + c);
        float4 av = *(const float4*)(ar + c);
        float4 dv = *(const float4*)(dr + c);
        s1 += hv.x * av.x + hv.y * av.y + hv.z * av.z + hv.w * av.w;
        s2 += hv.x * dv.x + hv.y * dv.y + hv.z * dv.z + hv.w * dv.w;
    }
#pragma unroll
    for (int o = 16; o; o >>= 1) {
        s1 += __shfl_xor_sync(0xffffffffu, s1, o);
        s2 += __shfl_xor_sync(0xffffffffu, s2, o);
    }
    if (lane == 0) { es[w] = s1; ed[w] = s2; }
}

// ---------------- fused attention aggregate + bias + BN(eval) + ReLU ---------
// one warp per (node, head); ew stash; proven round-6 version.
template <int C>
__global__ void k_att(const float* __restrict__ h, const float* __restrict__ es,
                      const float* __restrict__ ed, const float* __restrict__ bb,
                      const float* __restrict__ gg, const float* __restrict__ be,
                      const float* __restrict__ rm, const float* __restrict__ rv,
                      float* __restrict__ outp, bf16* __restrict__ ohi,
                      bf16* __restrict__ olo) {
    int gt = blockIdx.x * blockDim.x + threadIdx.x;
    int w = gt >> 5, lane = gt & 31;
    if (w >= NN * 2) return;
    int node = w >> 1, head = w & 1;
    int beg = g_off[node], end = g_off[node + 1];
    float edv = ed[node * 2 + head];
    float* ew = g_ew + (size_t)head * NET;

    // pass A: compute + stash leaky logits, track max
    float m = -1e30f;
    for (int j = beg + lane; j < end; j += 32) {
        int s = g_csr[j];
        float e = es[s * 2 + head] + edv;
        e = e > 0.f ? e : 0.2f * e;
        ew[j] = e;
        m = fmaxf(m, e);
    }
#pragma unroll
    for (int o = 16; o; o >>= 1) m = fmaxf(m, __shfl_xor_sync(0xffffffffu, m, o));

    // pass B: weighted feature accumulation
    float4 acc0 = make_float4(0.f, 0.f, 0.f, 0.f);
    float4 acc1 = make_float4(0.f, 0.f, 0.f, 0.f);
    float wsum = 0.f;
    for (int j0 = beg; j0 < end; j0 += 32) {
        int jj = j0 + lane;
        bool val = jj < end;
        int sl = val ? g_csr[jj] : 0;
        float wl = val ? __expf(ew[jj] - m) : 0.f;
        wsum += wl;
        int cnt = end - j0; if (cnt > 32) cnt = 32;
        for (int t = 0; t < cnt; t++) {
            float wv = __shfl_sync(0xffffffffu, wl, t);
            int   sv = __shfl_sync(0xffffffffu, sl, t);
            const float4* p = (const float4*)(h + (size_t)sv * (2 * C) + head * C) + lane;
            float4 v = __ldg(p);
            acc0.x += wv * v.x; acc0.y += wv * v.y;
            acc0.z += wv * v.z; acc0.w += wv * v.w;
            if (C == 256) {
                float4 v2 = __ldg(p + 32);
                acc1.x += wv * v2.x; acc1.y += wv * v2.y;
                acc1.z += wv * v2.z; acc1.w += wv * v2.w;
            }
        }
    }
#pragma unroll
    for (int o = 16; o; o >>= 1) wsum += __shfl_xor_sync(0xffffffffu, wsum, o);
    float inv = 1.0f / (wsum + 1e-16f);

    // epilogue: alpha-normalize, +bias, BN eval, ReLU (striped for C=256)
    int f0 = head * C + lane * 4;
    float res0[4];
    {
        float vals[4] = {acc0.x, acc0.y, acc0.z, acc0.w};
#pragma unroll
        for (int k = 0; k < 4; k++) {
            int f = f0 + k;
            float o = vals[k] * inv + bb[f];
            o = (o - rm[f]) * rsqrtf(rv[f] + 1e-5f) * gg[f] + be[f];
            res0[k] = fmaxf(o, 0.f);
        }
    }
    if (C == 128) {
        size_t idx = (size_t)node * (2 * C) + f0;
        bf16 h0 = __float2bfloat16(res0[0]);
        bf16 h1 = __float2bfloat16(res0[1]);
        bf16 h2 = __float2bfloat16(res0[2]);
        bf16 h3 = __float2bfloat16(res0[3]);
        __nv_bfloat162* ph = (__nv_bfloat162*)(ohi + idx);
        ph[0] = __nv_bfloat162(h0, h1);
        ph[1] = __nv_bfloat162(h2, h3);
        __nv_bfloat162* pl = (__nv_bfloat162*)(olo + idx);
        pl[0] = __nv_bfloat162(__float2bfloat16(res0[0] - __bfloat162float(h0)),
                               __float2bfloat16(res0[1] - __bfloat162float(h1)));
        pl[1] = __nv_bfloat162(__float2bfloat16(res0[2] - __bfloat162float(h2)),
                               __float2bfloat16(res0[3] - __bfloat162float(h3)));
    } else {
        *(float4*)(outp + (size_t)node * (2 * C) + f0) =
            make_float4(res0[0], res0[1], res0[2], res0[3]);
        int f1 = f0 + 128;
        float vals[4] = {acc1.x, acc1.y, acc1.z, acc1.w};
        float4 o4;
        float* ov = (float*)&o4;
#pragma unroll
        for (int k = 0; k < 4; k++) {
            int f = f1 + k;
            float o = vals[k] * inv + bb[f];
            o = (o - rm[f]) * rsqrtf(rv[f] + 1e-5f) * gg[f] + be[f];
            ov[k] = fmaxf(o, 0.f);
        }
        *(float4*)(outp + (size_t)node * (2 * C) + f1) = o4;
    }
}

// ---------------- launch -----------------------------------------------------
extern "C" void kernel_launch(void* const* d_in, const int* in_sizes, int n_in,
                              void* d_out, int out_size) {
    const float* x   = (const float*)d_in[0];
    const int*   ei  = (const int*)d_in[1];
    const float* W1  = (const float*)d_in[2];
    const float* as1 = (const float*)d_in[3];
    const float* ad1 = (const float*)d_in[4];
    const float* b1  = (const float*)d_in[5];
    const float* g1  = (const float*)d_in[6];
    const float* be1 = (const float*)d_in[7];
    const float* m1  = (const float*)d_in[8];
    const float* v1  = (const float*)d_in[9];
    const float* W2  = (const float*)d_in[10];
    const float* as2 = (const float*)d_in[11];
    const float* ad2 = (const float*)d_in[12];
    const float* b2  = (const float*)d_in[13];
    const float* g2  = (const float*)d_in[14];
    const float* be2 = (const float*)d_in[15];
    const float* m2  = (const float*)d_in[16];
    const float* v2  = (const float*)d_in[17];
    float* out = (float*)d_out;

    const int* srcp = ei;
    const int* dstp = ei + NE;

    float *h1, *h2;
    cudaGetSymbolAddress((void**)&h1, g_h1);
    cudaGetSymbolAddress((void**)&h2, g_h2);
    bf16 *xhi, *xlo, *f1hi, *f1lo, *w1hi, *w1lo, *w2hi, *w2lo;
    cudaGetSymbolAddress((void**)&xhi, g_xhi);
    cudaGetSymbolAddress((void**)&xlo, g_xlo);
    cudaGetSymbolAddress((void**)&f1hi, g_f1hi);
    cudaGetSymbolAddress((void**)&f1lo, g_f1lo);
    cudaGetSymbolAddress((void**)&w1hi, g_w1hi);
    cudaGetSymbolAddress((void**)&w1lo, g_w1lo);
    cudaGetSymbolAddress((void**)&w2hi, g_w2hi);
    cudaGetSymbolAddress((void**)&w2lo, g_w2lo);
    float *es1, *ed1, *es2, *ed2;
    cudaGetSymbolAddress((void**)&es1, g_es1);
    cudaGetSymbolAddress((void**)&ed1, g_ed1);
    cudaGetSymbolAddress((void**)&es2, g_es2);
    cudaGetSymbolAddress((void**)&ed2, g_ed2);

    static bool attrSet = false;
    if (!attrSet) {
        cudaFuncSetAttribute(k_mma, cudaFuncAttributeMaxDynamicSharedMemorySize,
                             2 * BUFB);
        attrSet = true;
    }

    const int warpBlocks = (NN * 2 * 32) / 256;   // 12500 (warp per node-head)
    const int mTiles = (NN + 127) / 128;          // 391

    // launches 0..2: conversions (k_split also zeroes g_deg)
    k_splitT<<<(128 * 256 + 255) / 256, 256>>>(W1, w1hi, w1lo, 128, 256);
    k_splitT<<<(256 * 512 + 255) / 256, 256>>>(W2, w2hi, w2lo, 256, 512);
    k_split<<<(NN * 128 + 255) / 256, 256>>>(x, xhi, xlo, NN * 128);

    // launch 3: layer-1 GEMM (ncu lands here)
    k_mma<<<dim3(4, mTiles), 256, 2 * BUFB>>>(xhi, xlo, w1hi, w1lo, h1, NN, 256, 128);

    // CSR build
    k_hist<<<(NET + 255) / 256, 256>>>(dstp);
    k_scan<<<1, 1024>>>();
    k_fill<<<(NET + 255) / 256, 256>>>(srcp, dstp);

    // layer 1 attention
    k_edot<128><<<warpBlocks, 256>>>(h1, as1, ad1, es1, ed1);
    k_att<128><<<warpBlocks, 256>>>(h1, es1, ed1, b1, g1, be1, m1, v1, nullptr, f1hi, f1lo);

    // layer 2
    k_mma<<<dim3(8, mTiles), 256, 2 * BUFB>>>(f1hi, f1lo, w2hi, w2lo, h2, NN, 512, 256);
    k_edot<256><<<warpBlocks, 256>>>(h2, as2, ad2, es2, ed2);
    k_att<256><<<warpBlocks, 256>>>(h2, es2, ed2, b2, g2, be2, m2, v2, out, nullptr, nullptr);
}

// round 12
// speedup vs baseline: 1.0783x; 1.0496x over previous
#include <cuda_runtime.h>
#include <cuda_bf16.h>
#include <cuda_fp16.h>
#include <cstdint>

#define NN  50000
#define NE  800000
#define NET 850000   // NE + NN self loops

typedef __half fp16;

// ---------------- scratch (static device globals; no allocs allowed) ----------
__device__ float g_h1[(size_t)NN * 256];   // x @ W1 (f32, gather source)
__device__ float g_h2[(size_t)NN * 512];   // f1 @ W2 (f32, gather source)
__device__ fp16  g_xhi[(size_t)NN * 128], g_xlo[(size_t)NN * 128];
__device__ fp16  g_f1hi[(size_t)NN * 256], g_f1lo[(size_t)NN * 256];
__device__ fp16  g_w1[256 * 128];          // W1^T [N=256,K=128] fp16
__device__ fp16  g_w2[512 * 256];          // W2^T [N=512,K=256] fp16
__device__ float g_es1[NN * 2], g_ed1[NN * 2];
__device__ float g_es2[NN * 2], g_ed2[NN * 2];
__device__ float g_ew[(size_t)2 * NET];    // per-(head,edge) leaky logits
__device__ int   g_deg[NN];
__device__ int   g_off[NN + 1];
__device__ int   g_cur[NN];
__device__ int   g_csr[NET];               // src per CSR slot (grouped by dst)

// ---------------- PTX helpers (arch-generic: ldmatrix + mma.sync) -------------
__device__ __forceinline__ uint32_t s2u(const void* p) {
    uint32_t a;
    asm("{ .reg .u64 t; cvta.to.shared.u64 t, %1; cvt.u32.u64 %0, t; }"
        : "=r"(a) : "l"(p));
    return a;
}

__device__ __forceinline__ void ldsm4(uint32_t* r, uint32_t addr) {
    asm volatile("ldmatrix.sync.aligned.m8n8.x4.shared.b16 {%0,%1,%2,%3}, [%4];"
                 : "=r"(r[0]), "=r"(r[1]), "=r"(r[2]), "=r"(r[3]) : "r"(addr));
}

__device__ __forceinline__ void mma16816h(float* d, const uint32_t* a,
                                          uint32_t b0, uint32_t b1) {
    asm volatile(
        "mma.sync.aligned.m16n8k16.row.col.f32.f16.f16.f32 "
        "{%0,%1,%2,%3}, {%4,%5,%6,%7}, {%8,%9}, {%0,%1,%2,%3};"
        : "+f"(d[0]), "+f"(d[1]), "+f"(d[2]), "+f"(d[3])
        : "r"(a[0]), "r"(a[1]), "r"(a[2]), "r"(a[3]), "r"(b0), "r"(b1));
}

// ---------------- fp32 -> fp16 hi/lo split (+fused g_deg zero) ----------------
__global__ void k_split(const float* __restrict__ in, fp16* __restrict__ hi,
                        fp16* __restrict__ lo, int n) {
    int i = blockIdx.x * blockDim.x + threadIdx.x;
    if (i < NN) g_deg[i] = 0;
    if (i >= n) return;
    float v = in[i];
    fp16 h = __float2half_rn(v);
    hi[i] = h;
    lo[i] = __float2half_rn(v - __half2float(h));
}

// W[K,N] row-major -> Wt[N,K] fp16 (single)
__global__ void k_cvtT(const float* __restrict__ W, fp16* __restrict__ T,
                       int K, int N) {
    int i = blockIdx.x * blockDim.x + threadIdx.x;
    if (i >= K * N) return;
    int k = i / N, n = i % N;
    T[(size_t)n * K + k] = __float2half_rn(W[i]);
}

// ---------------- CSR build (proven versions) ---------------------------------
__global__ void k_hist(const int* __restrict__ dst) {
    int i = blockIdx.x * blockDim.x + threadIdx.x;
    if (i >= NET) return;
    int d = (i < NE) ? dst[i] : (i - NE);
    atomicAdd(&g_deg[d], 1);
}

__global__ void k_scan() {
    __shared__ int sums[1024];
    const int t  = threadIdx.x;
    const int CH = (NN + 1023) / 1024;
    int b = t * CH, e = b + CH; if (e > NN) e = NN; if (b > NN) b = NN;
    int s = 0;
    for (int i = b; i < e; i++) s += g_deg[i];
    sums[t] = s;
    __syncthreads();
    for (int off = 1; off < 1024; off <<= 1) {
        int v = (t >= off) ? sums[t - off] : 0;
        __syncthreads();
        sums[t] += v;
        __syncthreads();
    }
    int pre = (t == 0) ? 0 : sums[t - 1];
    for (int i = b; i < e; i++) {
        g_off[i] = pre;
        g_cur[i] = pre;
        pre += g_deg[i];
    }
    if (t == 1023) g_off[NN] = NET;
}

__global__ void k_fill(const int* __restrict__ src, const int* __restrict__ dst) {
    int i = blockIdx.x * blockDim.x + threadIdx.x;
    if (i >= NET) return;
    int s, d;
    if (i < NE) { s = src[i]; d = dst[i]; }
    else        { s = d = i - NE; }
    int pos = atomicAdd(&g_cur[d], 1);
    g_csr[pos] = s;
}

// ---------------- HMMA GEMM v4: C[M,Nn] = A[M,K] @ Wt[Nn,K]^T -----------------
// fp16 2-product split: C = Ahi*B + Alo*B (fp32 acc), fp32 output.
// 256 threads, 128x64 tile, 8 warps (4x2), warp tile 32x32.
// Double-buffered dynamic smem, one sync per chunk; 2 CTAs/SM.
#define RS 40              // smem row stride in 16-bit elems (80B, conflict-free)
#define ARRA 10240         // A array bytes (128*RS*2)
#define ARRB2 5120         // B array bytes (64*RS*2)
#define BUFB (2*ARRA + ARRB2)   // 25600 per buffer
#define OFF_AH 0
#define OFF_AL ARRA
#define OFF_BH (2*ARRA)

__global__ __launch_bounds__(256)
void k_mma(const fp16* __restrict__ Ahi, const fp16* __restrict__ Alo,
           const fp16* __restrict__ B,
           float* __restrict__ C, int M, int Nn, int K) {
    extern __shared__ __align__(16) char smem[];

    const int tid = threadIdx.x, lane = tid & 31, wid = tid >> 5;
    const int bm = blockIdx.y * 128, bn = blockIdx.x * 64;
    const int wm = (wid & 3) * 32;
    const int wn = (wid >> 2) * 32;

    // gmem loaders.  A: 2 rounds x (hi,lo); rows 0..127, 32 cols per chunk.
    int arow[2];
    size_t aoff[2];
#pragma unroll
    for (int r = 0; r < 2; r++) {
        int idx = tid + r * 256;
        arow[r] = idx >> 2;
        int ra = bm + arow[r]; if (ra >= M) ra = M - 1;
        aoff[r] = (size_t)ra * K + (idx & 3) * 8;
    }
    // B: 1 round; rows 0..63
    const int brow = tid >> 2;
    const size_t boff = (size_t)(bn + brow) * K + (tid & 3) * 8;

    const uint32_t soA0 = (uint32_t)((arow[0] * RS + (tid & 3) * 8) * 2);
    const uint32_t soA1 = (uint32_t)((arow[1] * RS + ((tid + 256) & 3) * 8) * 2);
    const uint32_t soB  = (uint32_t)((brow * RS + (tid & 3) * 8) * 2);

    // ldmatrix per-lane base byte offsets within arrays
    const int li = lane >> 3, l8 = lane & 7;
    const uint32_t aA = (uint32_t)(((wm + (li & 1) * 8 + l8) * RS + (li >> 1) * 8) * 2);
    const uint32_t aB = (uint32_t)(((wn + (li >> 1) * 8 + l8) * RS + (li & 1) * 8) * 2);
    const uint32_t base = s2u(smem);

    float acc[2][4][4];
#pragma unroll
    for (int i = 0; i < 2; i++)
#pragma unroll
        for (int j = 0; j < 4; j++)
#pragma unroll
            for (int k = 0; k < 4; k++) acc[i][j][k] = 0.f;

    uint4 pfA[2][2], pfB;
    const int nch = K >> 5;

#pragma unroll
    for (int r = 0; r < 2; r++) {
        pfA[0][r] = *(const uint4*)(Ahi + aoff[r]);
        pfA[1][r] = *(const uint4*)(Alo + aoff[r]);
    }
    pfB = *(const uint4*)(B + boff);

    for (int c = 0; c < nch; c++) {
        const uint32_t bufo = (uint32_t)((c & 1) * BUFB);
        char* pb = smem + bufo;
        *(uint4*)(pb + OFF_AH + soA0) = pfA[0][0];
        *(uint4*)(pb + OFF_AH + soA1) = pfA[0][1];
        *(uint4*)(pb + OFF_AL + soA0) = pfA[1][0];
        *(uint4*)(pb + OFF_AL + soA1) = pfA[1][1];
        *(uint4*)(pb + OFF_BH + soB)  = pfB;
        __syncthreads();

        if (c + 1 < nch) {
            size_t kadv = (size_t)(c + 1) * 32;
#pragma unroll
            for (int r = 0; r < 2; r++) {
                pfA[0][r] = *(const uint4*)(Ahi + aoff[r] + kadv);
                pfA[1][r] = *(const uint4*)(Alo + aoff[r] + kadv);
            }
            pfB = *(const uint4*)(B + boff + kadv);
        }

        const uint32_t bAh = base + bufo + OFF_AH + aA;
        const uint32_t bAl = base + bufo + OFF_AL + aA;
        const uint32_t bBh = base + bufo + OFF_BH + aB;

#pragma unroll
        for (int ks = 0; ks < 2; ks++) {
            const uint32_t kb = (uint32_t)(ks * 16 * 2);
            uint32_t ah[2][4], al[2][4], bh[2][4];
#pragma unroll
            for (int mt = 0; mt < 2; mt++) {
                uint32_t off = (uint32_t)(mt * 16 * RS * 2) + kb;
                ldsm4(ah[mt], bAh + off);
                ldsm4(al[mt], bAl + off);
            }
#pragma unroll
            for (int p = 0; p < 2; p++) {
                uint32_t off = (uint32_t)(p * 16 * RS * 2) + kb;
                ldsm4(bh[p], bBh + off);
            }
#pragma unroll
            for (int mt = 0; mt < 2; mt++)
#pragma unroll
                for (int nt = 0; nt < 4; nt++) {
                    const int p = nt >> 1, o = (nt & 1) * 2;
                    mma16816h(acc[mt][nt], ah[mt], bh[p][o], bh[p][o + 1]);
                    mma16816h(acc[mt][nt], al[mt], bh[p][o], bh[p][o + 1]);
                }
        }
        // no trailing sync: next iteration writes the OTHER buffer
    }

#pragma unroll
    for (int mt = 0; mt < 2; mt++) {
        int r0 = bm + wm + mt * 16 + (lane >> 2);
#pragma unroll
        for (int nt = 0; nt < 4; nt++) {
            int col = bn + wn + nt * 8 + (lane & 3) * 2;
            if (r0 < M)
                *(float2*)(C + (size_t)r0 * Nn + col) =
                    make_float2(acc[mt][nt][0], acc[mt][nt][1]);
            if (r0 + 8 < M)
                *(float2*)(C + (size_t)(r0 + 8) * Nn + col) =
                    make_float2(acc[mt][nt][2], acc[mt][nt][3]);
        }
    }
}

// ---------------- per-(node,head) attention coefficients e_src/e_dst ---------
template <int C>
__global__ void k_edot(const float* __restrict__ h, const float* __restrict__ as_,
                       const float* __restrict__ ad_, float* __restrict__ es,
                       float* __restrict__ ed) {
    int gt = blockIdx.x * blockDim.x + threadIdx.x;
    int w = gt >> 5, lane = gt & 31;
    if (w >= NN * 2) return;
    int node = w >> 1, head = w & 1;
    const float* hr = h + (size_t)node * (2 * C) + head * C;
    const float* ar = as_ + head * C;
    const float* dr = ad_ + head * C;
    float s1 = 0.f, s2 = 0.f;
#pragma unroll
    for (int c = lane * 4; c < C; c += 128) {
        float4 hv = *(const float4*)(hr + c);
        float4 av = *(const float4*)(ar + c);
        float4 dv = *(const float4*)(dr + c);
        s1 += hv.x * av.x + hv.y * av.y + hv.z * av.z + hv.w * av.w;
        s2 += hv.x * dv.x + hv.y * dv.y + hv.z * dv.z + hv.w * dv.w;
    }
#pragma unroll
    for (int o = 16; o; o >>= 1) {
        s1 += __shfl_xor_sync(0xffffffffu, s1, o);
        s2 += __shfl_xor_sync(0xffffffffu, s2, o);
    }
    if (lane == 0) { es[w] = s1; ed[w] = s2; }
}

// ---------------- fused attention aggregate + bias + BN(eval) + ReLU ---------
// one warp per (node, head); ew stash; proven round-6 version.
// C==128: writes fp16 hi/lo (feeds next GEMM).  C==256: writes f32 to out.
template <int C>
__global__ void k_att(const float* __restrict__ h, const float* __restrict__ es,
                      const float* __restrict__ ed, const float* __restrict__ bb,
                      const float* __restrict__ gg, const float* __restrict__ be,
                      const float* __restrict__ rm, const float* __restrict__ rv,
                      float* __restrict__ outp, fp16* __restrict__ ohi,
                      fp16* __restrict__ olo) {
    int gt = blockIdx.x * blockDim.x + threadIdx.x;
    int w = gt >> 5, lane = gt & 31;
    if (w >= NN * 2) return;
    int node = w >> 1, head = w & 1;
    int beg = g_off[node], end = g_off[node + 1];
    float edv = ed[node * 2 + head];
    float* ew = g_ew + (size_t)head * NET;

    // pass A: compute + stash leaky logits, track max
    float m = -1e30f;
    for (int j = beg + lane; j < end; j += 32) {
        int s = g_csr[j];
        float e = es[s * 2 + head] + edv;
        e = e > 0.f ? e : 0.2f * e;
        ew[j] = e;
        m = fmaxf(m, e);
    }
#pragma unroll
    for (int o = 16; o; o >>= 1) m = fmaxf(m, __shfl_xor_sync(0xffffffffu, m, o));

    // pass B: weighted feature accumulation
    float4 acc0 = make_float4(0.f, 0.f, 0.f, 0.f);
    float4 acc1 = make_float4(0.f, 0.f, 0.f, 0.f);
    float wsum = 0.f;
    for (int j0 = beg; j0 < end; j0 += 32) {
        int jj = j0 + lane;
        bool val = jj < end;
        int sl = val ? g_csr[jj] : 0;
        float wl = val ? __expf(ew[jj] - m) : 0.f;
        wsum += wl;
        int cnt = end - j0; if (cnt > 32) cnt = 32;
        for (int t = 0; t < cnt; t++) {
            float wv = __shfl_sync(0xffffffffu, wl, t);
            int   sv = __shfl_sync(0xffffffffu, sl, t);
            const float4* p = (const float4*)(h + (size_t)sv * (2 * C) + head * C) + lane;
            float4 v = __ldg(p);
            acc0.x += wv * v.x; acc0.y += wv * v.y;
            acc0.z += wv * v.z; acc0.w += wv * v.w;
            if (C == 256) {
                float4 v2 = __ldg(p + 32);
                acc1.x += wv * v2.x; acc1.y += wv * v2.y;
                acc1.z += wv * v2.z; acc1.w += wv * v2.w;
            }
        }
    }
#pragma unroll
    for (int o = 16; o; o >>= 1) wsum += __shfl_xor_sync(0xffffffffu, wsum, o);
    float inv = 1.0f / (wsum + 1e-16f);

    // epilogue: alpha-normalize, +bias, BN eval, ReLU (striped for C=256)
    int f0 = head * C + lane * 4;
    float res0[4];
    {
        float vals[4] = {acc0.x, acc0.y, acc0.z, acc0.w};
#pragma unroll
        for (int k = 0; k < 4; k++) {
            int f = f0 + k;
            float o = vals[k] * inv + bb[f];
            o = (o - rm[f]) * rsqrtf(rv[f] + 1e-5f) * gg[f] + be[f];
            res0[k] = fmaxf(o, 0.f);
        }
    }
    if (C == 128) {
        size_t idx = (size_t)node * (2 * C) + f0;
        fp16 h0 = __float2half_rn(res0[0]);
        fp16 h1 = __float2half_rn(res0[1]);
        fp16 h2 = __float2half_rn(res0[2]);
        fp16 h3 = __float2half_rn(res0[3]);
        __half2* ph = (__half2*)(ohi + idx);
        ph[0] = __halves2half2(h0, h1);
        ph[1] = __halves2half2(h2, h3);
        __half2* pl = (__half2*)(olo + idx);
        pl[0] = __halves2half2(__float2half_rn(res0[0] - __half2float(h0)),
                               __float2half_rn(res0[1] - __half2float(h1)));
        pl[1] = __halves2half2(__float2half_rn(res0[2] - __half2float(h2)),
                               __float2half_rn(res0[3] - __half2float(h3)));
    } else {
        *(float4*)(outp + (size_t)node * (2 * C) + f0) =
            make_float4(res0[0], res0[1], res0[2], res0[3]);
        int f1 = f0 + 128;
        float vals[4] = {acc1.x, acc1.y, acc1.z, acc1.w};
        float4 o4;
        float* ov = (float*)&o4;
#pragma unroll
        for (int k = 0; k < 4; k++) {
            int f = f1 + k;
            float o = vals[k] * inv + bb[f];
            o = (o - rm[f]) * rsqrtf(rv[f] + 1e-5f) * gg[f] + be[f];
            ov[k] = fmaxf(o, 0.f);
        }
        *(float4*)(outp + (size_t)node * (2 * C) + f1) = o4;
    }
}

// ---------------- launch -----------------------------------------------------
extern "C" void kernel_launch(void* const* d_in, const int* in_sizes, int n_in,
                              void* d_out, int out_size) {
    const float* x   = (const float*)d_in[0];
    const int*   ei  = (const int*)d_in[1];
    const float* W1  = (const float*)d_in[2];
    const float* as1 = (const float*)d_in[3];
    const float* ad1 = (const float*)d_in[4];
    const float* b1  = (const float*)d_in[5];
    const float* g1  = (const float*)d_in[6];
    const float* be1 = (const float*)d_in[7];
    const float* m1  = (const float*)d_in[8];
    const float* v1  = (const float*)d_in[9];
    const float* W2  = (const float*)d_in[10];
    const float* as2 = (const float*)d_in[11];
    const float* ad2 = (const float*)d_in[12];
    const float* b2  = (const float*)d_in[13];
    const float* g2  = (const float*)d_in[14];
    const float* be2 = (const float*)d_in[15];
    const float* m2  = (const float*)d_in[16];
    const float* v2  = (const float*)d_in[17];
    float* out = (float*)d_out;

    const int* srcp = ei;
    const int* dstp = ei + NE;

    float *h1, *h2;
    cudaGetSymbolAddress((void**)&h1, g_h1);
    cudaGetSymbolAddress((void**)&h2, g_h2);
    fp16 *xhi, *xlo, *f1hi, *f1lo, *w1, *w2;
    cudaGetSymbolAddress((void**)&xhi, g_xhi);
    cudaGetSymbolAddress((void**)&xlo, g_xlo);
    cudaGetSymbolAddress((void**)&f1hi, g_f1hi);
    cudaGetSymbolAddress((void**)&f1lo, g_f1lo);
    cudaGetSymbolAddress((void**)&w1, g_w1);
    cudaGetSymbolAddress((void**)&w2, g_w2);
    float *es1, *ed1, *es2, *ed2;
    cudaGetSymbolAddress((void**)&es1, g_es1);
    cudaGetSymbolAddress((void**)&ed1, g_ed1);
    cudaGetSymbolAddress((void**)&es2, g_es2);
    cudaGetSymbolAddress((void**)&ed2, g_ed2);

    static bool attrSet = false;
    if (!attrSet) {
        cudaFuncSetAttribute(k_mma, cudaFuncAttributeMaxDynamicSharedMemorySize,
                             2 * BUFB);
        attrSet = true;
    }

    const int warpBlocks = (NN * 2 * 32) / 256;   // 12500 (warp per node-head)
    const int mTiles = (NN + 127) / 128;          // 391

    // launches 0..2: conversions (k_split also zeroes g_deg)
    k_cvtT<<<(128 * 256 + 255) / 256, 256>>>(W1, w1, 128, 256);
    k_cvtT<<<(256 * 512 + 255) / 256, 256>>>(W2, w2, 256, 512);
    k_split<<<(NN * 128 + 255) / 256, 256>>>(x, xhi, xlo, NN * 128);

    // launch 3: layer-1 GEMM (ncu lands here)
    k_mma<<<dim3(4, mTiles), 256, 2 * BUFB>>>(xhi, xlo, w1, h1, NN, 256, 128);

    // CSR build
    k_hist<<<(NET + 255) / 256, 256>>>(dstp);
    k_scan<<<1, 1024>>>();
    k_fill<<<(NET + 255) / 256, 256>>>(srcp, dstp);

    // layer 1 attention
    k_edot<128><<<warpBlocks, 256>>>(h1, as1, ad1, es1, ed1);
    k_att<128><<<warpBlocks, 256>>>(h1, es1, ed1, b1, g1, be1, m1, v1, nullptr, f1hi, f1lo);

    // layer 2
    k_mma<<<dim3(8, mTiles), 256, 2 * BUFB>>>(f1hi, f1lo, w2, h2, NN, 512, 256);
    k_edot<256><<<warpBlocks, 256>>>(h2, as2, ad2, es2, ed2);
    k_att<256><<<warpBlocks, 256>>>(h2, es2, ed2, b2, g2, be2, m2, v2, out, nullptr, nullptr);
}

// round 13
// speedup vs baseline: 1.3514x; 1.2533x over previous
#include <cuda_runtime.h>
#include <cuda_fp16.h>
#include <cstdint>

#define NN  50000
#define NE  800000
#define NET 850000   // NE + NN self loops

typedef __half fp16;

// ---------------- scratch (static device globals; no allocs allowed) ----------
__device__ float g_f1[(size_t)NN * 256];     // layer-1 output (f32, gather source)
__device__ fp16  g_a1hi[(size_t)NN * 256], g_a1lo[(size_t)NN * 256];  // agg1 split
__device__ fp16  g_a2hi[(size_t)NN * 512], g_a2lo[(size_t)NN * 512];  // agg2 split
__device__ fp16  g_w1[256 * 128];            // W1^T [N=256,K=128] fp16
__device__ fp16  g_w2[512 * 256];            // W2^T [N=512,K=256] fp16
__device__ float g_vas1[2 * 128], g_vad1[2 * 128];   // W1_h @ a vectors
__device__ float g_vas2[2 * 256], g_vad2[2 * 256];
__device__ float g_sc1[256], g_sh1[256];     // fused bias+BN scale/shift
__device__ float g_sc2[512], g_sh2[512];
__device__ float g_es1[NN * 2], g_ed1[NN * 2];
__device__ float g_es2[NN * 2], g_ed2[NN * 2];
__device__ float g_ew[(size_t)2 * NET];      // per-edge (head0,head1) leaky logits
__device__ int   g_deg[NN];
__device__ int   g_off[NN + 1];
__device__ int   g_cur[NN];
__device__ int   g_csr[NET];                 // src per CSR slot (grouped by dst)

// ---------------- PTX helpers (arch-generic: ldmatrix + mma.sync) -------------
__device__ __forceinline__ uint32_t s2u(const void* p) {
    uint32_t a;
    asm("{ .reg .u64 t; cvta.to.shared.u64 t, %1; cvt.u32.u64 %0, t; }"
        : "=r"(a) : "l"(p));
    return a;
}

__device__ __forceinline__ void ldsm4(uint32_t* r, uint32_t addr) {
    asm volatile("ldmatrix.sync.aligned.m8n8.x4.shared.b16 {%0,%1,%2,%3}, [%4];"
                 : "=r"(r[0]), "=r"(r[1]), "=r"(r[2]), "=r"(r[3]) : "r"(addr));
}

__device__ __forceinline__ void mma16816h(float* d, const uint32_t* a,
                                          uint32_t b0, uint32_t b1) {
    asm volatile(
        "mma.sync.aligned.m16n8k16.row.col.f32.f16.f16.f32 "
        "{%0,%1,%2,%3}, {%4,%5,%6,%7}, {%8,%9}, {%0,%1,%2,%3};"
        : "+f"(d[0]), "+f"(d[1]), "+f"(d[2]), "+f"(d[3])
        : "r"(a[0]), "r"(a[1]), "r"(a[2]), "r"(a[3]), "r"(b0), "r"(b1));
}

// ---------------- W^T fp16 conversion -----------------------------------------
__global__ void k_cvtT(const float* __restrict__ W, fp16* __restrict__ T,
                       int K, int N) {
    int i = blockIdx.x * blockDim.x + threadIdx.x;
    if (i >= K * N) return;
    int k = i / N, n = i % N;
    T[(size_t)n * K + k] = __float2half_rn(W[i]);
}

// ---------------- prep: deg zero + va vectors + BN coefs ----------------------
__global__ void k_pre(const float* __restrict__ W1, const float* __restrict__ as1,
                      const float* __restrict__ ad1,
                      const float* __restrict__ W2, const float* __restrict__ as2,
                      const float* __restrict__ ad2,
                      const float* __restrict__ b1, const float* __restrict__ g1,
                      const float* __restrict__ be1, const float* __restrict__ m1,
                      const float* __restrict__ v1,
                      const float* __restrict__ b2, const float* __restrict__ g2,
                      const float* __restrict__ be2, const float* __restrict__ m2,
                      const float* __restrict__ v2) {
    int i = blockIdx.x * blockDim.x + threadIdx.x;
    if (i < NN) g_deg[i] = 0;
    // va1: [2,128]  va1[h,k] = sum_c W1[k, h*128+c] * a1[h,c]
    if (i < 256) {
        int h = i >> 7, k = i & 127;
        float s = 0.f, d = 0.f;
        const float* wr = W1 + (size_t)k * 256 + h * 128;
        const float* ar = as1 + h * 128;
        const float* dr = ad1 + h * 128;
        for (int c = 0; c < 128; c++) { s += wr[c] * ar[c]; d += wr[c] * dr[c]; }
        g_vas1[i] = s; g_vad1[i] = d;
    }
    // va2: [2,256]
    if (i >= 1024 && i < 1024 + 512) {
        int j = i - 1024, h = j >> 8, k = j & 255;
        float s = 0.f, d = 0.f;
        const float* wr = W2 + (size_t)k * 512 + h * 256;
        const float* ar = as2 + h * 256;
        const float* dr = ad2 + h * 256;
        for (int c = 0; c < 256; c++) { s += wr[c] * ar[c]; d += wr[c] * dr[c]; }
        g_vas2[j] = s; g_vad2[j] = d;
    }
    // BN coefs layer 1
    if (i >= 2048 && i < 2048 + 256) {
        int f = i - 2048;
        float sc = rsqrtf(v1[f] + 1e-5f) * g1[f];
        g_sc1[f] = sc;
        g_sh1[f] = (b1[f] - m1[f]) * sc + be1[f];
    }
    // BN coefs layer 2
    if (i >= 4096 && i < 4096 + 512) {
        int f = i - 4096;
        float sc = rsqrtf(v2[f] + 1e-5f) * g2[f];
        g_sc2[f] = sc;
        g_sh2[f] = (b2[f] - m2[f]) * sc + be2[f];
    }
}

// ---------------- CSR build (proven versions) ---------------------------------
__global__ void k_hist(const int* __restrict__ dst) {
    int i = blockIdx.x * blockDim.x + threadIdx.x;
    if (i >= NET) return;
    int d = (i < NE) ? dst[i] : (i - NE);
    atomicAdd(&g_deg[d], 1);
}

__global__ void k_scan() {
    __shared__ int sums[1024];
    const int t  = threadIdx.x;
    const int CH = (NN + 1023) / 1024;
    int b = t * CH, e = b + CH; if (e > NN) e = NN; if (b > NN) b = NN;
    int s = 0;
    for (int i = b; i < e; i++) s += g_deg[i];
    sums[t] = s;
    __syncthreads();
    for (int off = 1; off < 1024; off <<= 1) {
        int v = (t >= off) ? sums[t - off] : 0;
        __syncthreads();
        sums[t] += v;
        __syncthreads();
    }
    int pre = (t == 0) ? 0 : sums[t - 1];
    for (int i = b; i < e; i++) {
        g_off[i] = pre;
        g_cur[i] = pre;
        pre += g_deg[i];
    }
    if (t == 1023) g_off[NN] = NET;
}

__global__ void k_fill(const int* __restrict__ src, const int* __restrict__ dst) {
    int i = blockIdx.x * blockDim.x + threadIdx.x;
    if (i >= NET) return;
    int s, d;
    if (i < NE) { s = src[i]; d = dst[i]; }
    else        { s = d = i - NE; }
    int pos = atomicAdd(&g_cur[d], 1);
    g_csr[pos] = s;
}

// ---------------- logits: es/ed = feat . va, warp per node, 4 dots ------------
template <int K>
__global__ void k_edx(const float* __restrict__ feat, const float* __restrict__ vas,
                      const float* __restrict__ vad, float* __restrict__ es,
                      float* __restrict__ ed) {
    constexpr int NF4 = K / 128;   // float4 rounds per lane (1 or 2)
    int gt = blockIdx.x * blockDim.x + threadIdx.x;
    int node = gt >> 5, lane = gt & 31;
    if (node >= NN) return;
    const float4* p = (const float4*)(feat + (size_t)node * K);
    float s0 = 0.f, d0 = 0.f, s1 = 0.f, d1 = 0.f;
#pragma unroll
    for (int q = 0; q < NF4; q++) {
        int idx4 = q * 32 + lane;           // float4 index within row
        float4 xv = p[idx4];
        const float4* ps0 = (const float4*)(vas) + idx4;
        const float4* ps1 = (const float4*)(vas + K) + idx4;
        const float4* pd0 = (const float4*)(vad) + idx4;
        const float4* pd1 = (const float4*)(vad + K) + idx4;
        float4 a0 = *ps0, a1 = *ps1, c0 = *pd0, c1 = *pd1;
        s0 += xv.x * a0.x + xv.y * a0.y + xv.z * a0.z + xv.w * a0.w;
        s1 += xv.x * a1.x + xv.y * a1.y + xv.z * a1.z + xv.w * a1.w;
        d0 += xv.x * c0.x + xv.y * c0.y + xv.z * c0.z + xv.w * c0.w;
        d1 += xv.x * c1.x + xv.y * c1.y + xv.z * c1.z + xv.w * c1.w;
    }
#pragma unroll
    for (int o = 16; o; o >>= 1) {
        s0 += __shfl_xor_sync(0xffffffffu, s0, o);
        s1 += __shfl_xor_sync(0xffffffffu, s1, o);
        d0 += __shfl_xor_sync(0xffffffffu, d0, o);
        d1 += __shfl_xor_sync(0xffffffffu, d1, o);
    }
    if (lane == 0) {
        es[node * 2]     = s0;
        es[node * 2 + 1] = s1;
        ed[node * 2]     = d0;
        ed[node * 2 + 1] = d1;
    }
}

// ---------------- attention aggregate over RAW features ----------------------
// ONE WARP PER NODE, both heads share the gathered source row.
// agg[node, h*K + k] = sum_e alpha_e[h] * feat[src_e, k]  (normalized),
// written as fp16 hi/lo split for the following GEMM.
template <int K>
__global__ void k_agg(const float* __restrict__ feat, const float* __restrict__ es,
                      const float* __restrict__ ed,
                      fp16* __restrict__ ahi, fp16* __restrict__ alo) {
    constexpr int VEC = K / 32;      // floats per lane (4 or 8)
    constexpr int NF4 = VEC / 4;     // float4s per lane (1 or 2)
    int gt = blockIdx.x * blockDim.x + threadIdx.x;
    int node = gt >> 5, lane = gt & 31;
    if (node >= NN) return;
    int beg = g_off[node], end = g_off[node + 1];
    float edv0 = ed[node * 2], edv1 = ed[node * 2 + 1];

    // pass A: both heads' leaky logits per edge; stash interleaved; track maxes
    float m0 = -1e30f, m1 = -1e30f;
    for (int j = beg + lane; j < end; j += 32) {
        int s = g_csr[j];
        float2 esv = *(const float2*)(es + 2 * s);
        float e0 = esv.x + edv0; e0 = e0 > 0.f ? e0 : 0.2f * e0;
        float e1 = esv.y + edv1; e1 = e1 > 0.f ? e1 : 0.2f * e1;
        *(float2*)(g_ew + 2 * (size_t)j) = make_float2(e0, e1);
        m0 = fmaxf(m0, e0);
        m1 = fmaxf(m1, e1);
    }
#pragma unroll
    for (int o = 16; o; o >>= 1) {
        m0 = fmaxf(m0, __shfl_xor_sync(0xffffffffu, m0, o));
        m1 = fmaxf(m1, __shfl_xor_sync(0xffffffffu, m1, o));
    }

    // pass B: weighted accumulation of the shared source row, both heads
    float acc0[VEC], acc1[VEC];
#pragma unroll
    for (int q = 0; q < VEC; q++) { acc0[q] = 0.f; acc1[q] = 0.f; }
    float ws0 = 0.f, ws1 = 0.f;

    for (int j0 = beg; j0 < end; j0 += 32) {
        int jj = j0 + lane;
        bool val = jj < end;
        int sl = val ? g_csr[jj] : 0;
        float wl0 = 0.f, wl1 = 0.f;
        if (val) {
            float2 e2 = *(const float2*)(g_ew + 2 * (size_t)jj);
            wl0 = __expf(e2.x - m0);
            wl1 = __expf(e2.y - m1);
        }
        ws0 += wl0; ws1 += wl1;
        int cnt = end - j0; if (cnt > 32) cnt = 32;
        for (int t = 0; t < cnt; t++) {
            int   sv = __shfl_sync(0xffffffffu, sl, t);
            float w0 = __shfl_sync(0xffffffffu, wl0, t);
            float w1 = __shfl_sync(0xffffffffu, wl1, t);
            const float4* p = (const float4*)(feat + (size_t)sv * K);
#pragma unroll
            for (int q = 0; q < NF4; q++) {
                float4 v = __ldg(p + q * 32 + lane);
                acc0[4 * q + 0] += w0 * v.x; acc0[4 * q + 1] += w0 * v.y;
                acc0[4 * q + 2] += w0 * v.z; acc0[4 * q + 3] += w0 * v.w;
                acc1[4 * q + 0] += w1 * v.x; acc1[4 * q + 1] += w1 * v.y;
                acc1[4 * q + 2] += w1 * v.z; acc1[4 * q + 3] += w1 * v.w;
            }
        }
    }
#pragma unroll
    for (int o = 16; o; o >>= 1) {
        ws0 += __shfl_xor_sync(0xffffffffu, ws0, o);
        ws1 += __shfl_xor_sync(0xffffffffu, ws1, o);
    }
    float inv0 = 1.0f / (ws0 + 1e-16f);
    float inv1 = 1.0f / (ws1 + 1e-16f);

    // epilogue: normalize + fp16 hi/lo split; feature index = q*128 + lane*4 + i
#pragma unroll
    for (int hd = 0; hd < 2; hd++) {
        const float* av = hd ? acc1 : acc0;
        float inv = hd ? inv1 : inv0;
#pragma unroll
        for (int q = 0; q < NF4; q++) {
            size_t idx = (size_t)node * (2 * K) + hd * K + q * 128 + lane * 4;
            float r0 = av[4 * q + 0] * inv;
            float r1 = av[4 * q + 1] * inv;
            float r2 = av[4 * q + 2] * inv;
            float r3 = av[4 * q + 3] * inv;
            fp16 h0 = __float2half_rn(r0);
            fp16 h1 = __float2half_rn(r1);
            fp16 h2 = __float2half_rn(r2);
            fp16 h3 = __float2half_rn(r3);
            __half2* ph = (__half2*)(ahi + idx);
            ph[0] = __halves2half2(h0, h1);
            ph[1] = __halves2half2(h2, h3);
            __half2* pl = (__half2*)(alo + idx);
            pl[0] = __halves2half2(__float2half_rn(r0 - __half2float(h0)),
                                   __float2half_rn(r1 - __half2float(h1)));
            pl[1] = __halves2half2(__float2half_rn(r2 - __half2float(h2)),
                                   __float2half_rn(r3 - __half2float(h3)));
        }
    }
}

// ---------------- HMMA GEMM v5: per-head, fused bias+BN+ReLU epilogue ---------
// C[r, z*CH + n] = relu( (A_z[r,:] . B_z[n,:]) * sc + sh ),  A = Ahi + Alo.
// A row stride ldA (=2K), head-z block at offset z*K.  B rows = Wt[z*CH + n].
// 256 threads, 128x64 tile, 8 warps (4x2), warp tile 32x32, double-buffered.
#define RS 40              // smem row stride in 16-bit elems (80B, conflict-free)
#define ARRA 10240         // A array bytes (128*RS*2)
#define ARRB2 5120         // B array bytes (64*RS*2)
#define BUFB (2*ARRA + ARRB2)   // 25600 per buffer
#define OFF_AH 0
#define OFF_AL ARRA
#define OFF_BH (2*ARRA)

__global__ __launch_bounds__(256)
void k_mma(const fp16* __restrict__ Ahi, const fp16* __restrict__ Alo,
           const fp16* __restrict__ B, float* __restrict__ C,
           const float* __restrict__ sc, const float* __restrict__ sh,
           int M, int K, int CH) {
    extern __shared__ __align__(16) char smem[];

    const int tid = threadIdx.x, lane = tid & 31, wid = tid >> 5;
    const int bm = blockIdx.y * 128;
    const int z  = blockIdx.z;
    const int bnl = blockIdx.x * 64;        // col offset within head
    const int ldA = 2 * K;
    const int wm = (wid & 3) * 32;
    const int wn = (wid >> 2) * 32;

    // gmem loaders.  A: 2 rounds x (hi,lo); rows 0..127, 32 cols per chunk.
    int arow[2];
    size_t aoff[2];
#pragma unroll
    for (int r = 0; r < 2; r++) {
        int idx = tid + r * 256;
        arow[r] = idx >> 2;
        int ra = bm + arow[r]; if (ra >= M) ra = M - 1;
        aoff[r] = (size_t)ra * ldA + z * K + (idx & 3) * 8;
    }
    // B: rows 0..63 of this head's tile
    const int brow = tid >> 2;
    const size_t boff = (size_t)(z * CH + bnl + brow) * K + (tid & 3) * 8;

    const uint32_t soA0 = (uint32_t)((arow[0] * RS + (tid & 3) * 8) * 2);
    const uint32_t soA1 = (uint32_t)((arow[1] * RS + ((tid + 256) & 3) * 8) * 2);
    const uint32_t soB  = (uint32_t)((brow * RS + (tid & 3) * 8) * 2);

    const int li = lane >> 3, l8 = lane & 7;
    const uint32_t aA = (uint32_t)(((wm + (li & 1) * 8 + l8) * RS + (li >> 1) * 8) * 2);
    const uint32_t aB = (uint32_t)(((wn + (li >> 1) * 8 + l8) * RS + (li & 1) * 8) * 2);
    const uint32_t base = s2u(smem);

    float acc[2][4][4];
#pragma unroll
    for (int i = 0; i < 2; i++)
#pragma unroll
        for (int j = 0; j < 4; j++)
#pragma unroll
            for (int k = 0; k < 4; k++) acc[i][j][k] = 0.f;

    uint4 pfA[2][2], pfB;
    const int nch = K >> 5;

#pragma unroll
    for (int r = 0; r < 2; r++) {
        pfA[0][r] = *(const uint4*)(Ahi + aoff[r]);
        pfA[1][r] = *(const uint4*)(Alo + aoff[r]);
    }
    pfB = *(const uint4*)(B + boff);

    for (int c = 0; c < nch; c++) {
        const uint32_t bufo = (uint32_t)((c & 1) * BUFB);
        char* pb = smem + bufo;
        *(uint4*)(pb + OFF_AH + soA0) = pfA[0][0];
        *(uint4*)(pb + OFF_AH + soA1) = pfA[0][1];
        *(uint4*)(pb + OFF_AL + soA0) = pfA[1][0];
        *(uint4*)(pb + OFF_AL + soA1) = pfA[1][1];
        *(uint4*)(pb + OFF_BH + soB)  = pfB;
        __syncthreads();

        if (c + 1 < nch) {
            size_t kadv = (size_t)(c + 1) * 32;
#pragma unroll
            for (int r = 0; r < 2; r++) {
                pfA[0][r] = *(const uint4*)(Ahi + aoff[r] + kadv);
                pfA[1][r] = *(const uint4*)(Alo + aoff[r] + kadv);
            }
            pfB = *(const uint4*)(B + boff + kadv);
        }

        const uint32_t bAh = base + bufo + OFF_AH + aA;
        const uint32_t bAl = base + bufo + OFF_AL + aA;
        const uint32_t bBh = base + bufo + OFF_BH + aB;

#pragma unroll
        for (int ks = 0; ks < 2; ks++) {
            const uint32_t kb = (uint32_t)(ks * 16 * 2);
            uint32_t ah[2][4], al[2][4], bh[2][4];
#pragma unroll
            for (int mt = 0; mt < 2; mt++) {
                uint32_t off = (uint32_t)(mt * 16 * RS * 2) + kb;
                ldsm4(ah[mt], bAh + off);
                ldsm4(al[mt], bAl + off);
            }
#pragma unroll
            for (int p = 0; p < 2; p++) {
                uint32_t off = (uint32_t)(p * 16 * RS * 2) + kb;
                ldsm4(bh[p], bBh + off);
            }
#pragma unroll
            for (int mt = 0; mt < 2; mt++)
#pragma unroll
                for (int nt = 0; nt < 4; nt++) {
                    const int p = nt >> 1, o = (nt & 1) * 2;
                    mma16816h(acc[mt][nt], ah[mt], bh[p][o], bh[p][o + 1]);
                    mma16816h(acc[mt][nt], al[mt], bh[p][o], bh[p][o + 1]);
                }
        }
        // no trailing sync: next iteration writes the OTHER buffer
    }

    // epilogue: fused scale/shift + ReLU; C row stride = 2*CH
    const int Ntot = 2 * CH;
#pragma unroll
    for (int mt = 0; mt < 2; mt++) {
        int r0 = bm + wm + mt * 16 + (lane >> 2);
#pragma unroll
        for (int nt = 0; nt < 4; nt++) {
            int col = z * CH + bnl + wn + nt * 8 + (lane & 3) * 2;
            float s0 = sc[col], s1 = sc[col + 1];
            float t0 = sh[col], t1 = sh[col + 1];
            if (r0 < M)
                *(float2*)(C + (size_t)r0 * Ntot + col) = make_float2(
                    fmaxf(acc[mt][nt][0] * s0 + t0, 0.f),
                    fmaxf(acc[mt][nt][1] * s1 + t1, 0.f));
            if (r0 + 8 < M)
                *(float2*)(C + (size_t)(r0 + 8) * Ntot + col) = make_float2(
                    fmaxf(acc[mt][nt][2] * s0 + t0, 0.f),
                    fmaxf(acc[mt][nt][3] * s1 + t1, 0.f));
        }
    }
}

// ---------------- launch -----------------------------------------------------
extern "C" void kernel_launch(void* const* d_in, const int* in_sizes, int n_in,
                              void* d_out, int out_size) {
    const float* x   = (const float*)d_in[0];
    const int*   ei  = (const int*)d_in[1];
    const float* W1  = (const float*)d_in[2];
    const float* as1 = (const float*)d_in[3];
    const float* ad1 = (const float*)d_in[4];
    const float* b1  = (const float*)d_in[5];
    const float* g1  = (const float*)d_in[6];
    const float* be1 = (const float*)d_in[7];
    const float* m1  = (const float*)d_in[8];
    const float* v1  = (const float*)d_in[9];
    const float* W2  = (const float*)d_in[10];
    const float* as2 = (const float*)d_in[11];
    const float* ad2 = (const float*)d_in[12];
    const float* b2  = (const float*)d_in[13];
    const float* g2  = (const float*)d_in[14];
    const float* be2 = (const float*)d_in[15];
    const float* m2  = (const float*)d_in[16];
    const float* v2  = (const float*)d_in[17];
    float* out = (float*)d_out;

    const int* srcp = ei;
    const int* dstp = ei + NE;

    float *f1;
    cudaGetSymbolAddress((void**)&f1, g_f1);
    fp16 *a1hi, *a1lo, *a2hi, *a2lo, *w1, *w2;
    cudaGetSymbolAddress((void**)&a1hi, g_a1hi);
    cudaGetSymbolAddress((void**)&a1lo, g_a1lo);
    cudaGetSymbolAddress((void**)&a2hi, g_a2hi);
    cudaGetSymbolAddress((void**)&a2lo, g_a2lo);
    cudaGetSymbolAddress((void**)&w1, g_w1);
    cudaGetSymbolAddress((void**)&w2, g_w2);
    float *vas1, *vad1, *vas2, *vad2, *sc1, *sh1, *sc2, *sh2;
    cudaGetSymbolAddress((void**)&vas1, g_vas1);
    cudaGetSymbolAddress((void**)&vad1, g_vad1);
    cudaGetSymbolAddress((void**)&vas2, g_vas2);
    cudaGetSymbolAddress((void**)&vad2, g_vad2);
    cudaGetSymbolAddress((void**)&sc1, g_sc1);
    cudaGetSymbolAddress((void**)&sh1, g_sh1);
    cudaGetSymbolAddress((void**)&sc2, g_sc2);
    cudaGetSymbolAddress((void**)&sh2, g_sh2);
    float *es1, *ed1, *es2, *ed2;
    cudaGetSymbolAddress((void**)&es1, g_es1);
    cudaGetSymbolAddress((void**)&ed1, g_ed1);
    cudaGetSymbolAddress((void**)&es2, g_es2);
    cudaGetSymbolAddress((void**)&ed2, g_ed2);

    static bool attrSet = false;
    if (!attrSet) {
        cudaFuncSetAttribute(k_mma, cudaFuncAttributeMaxDynamicSharedMemorySize,
                             2 * BUFB);
        attrSet = true;
    }

    const int nodeWarpBlocks = (NN * 32 + 255) / 256;   // 6250 (warp per node)
    const int mTiles = (NN + 127) / 128;                // 391

    // conversions + prep
    k_cvtT<<<(128 * 256 + 255) / 256, 256>>>(W1, w1, 128, 256);
    k_cvtT<<<(256 * 512 + 255) / 256, 256>>>(W2, w2, 256, 512);
    k_pre<<<(NN + 255) / 256, 256>>>(W1, as1, ad1, W2, as2, ad2,
                                     b1, g1, be1, m1, v1, b2, g2, be2, m2, v2);

    // CSR build
    k_hist<<<(NET + 255) / 256, 256>>>(dstp);
    k_scan<<<1, 1024>>>();
    k_fill<<<(NET + 255) / 256, 256>>>(srcp, dstp);

    // layer 1: logits on x, aggregate x, then GEMM (+fused bias/BN/ReLU) -> f1
    k_edx<128><<<nodeWarpBlocks, 256>>>(x, vas1, vad1, es1, ed1);
    k_agg<128><<<nodeWarpBlocks, 256>>>(x, es1, ed1, a1hi, a1lo);
    k_mma<<<dim3(2, mTiles, 2), 256, 2 * BUFB>>>(a1hi, a1lo, w1, f1, sc1, sh1,
                                                 NN, 128, 128);

    // layer 2: logits on f1, aggregate f1, then GEMM -> out
    k_edx<256><<<nodeWarpBlocks, 256>>>(f1, vas2, vad2, es2, ed2);
    k_agg<256><<<nodeWarpBlocks, 256>>>(f1, es2, ed2, a2hi, a2lo);
    k_mma<<<dim3(4, mTiles, 2), 256, 2 * BUFB>>>(a2hi, a2lo, w2, out, sc2, sh2,
                                                 NN, 256, 256);
}